// round 12
// baseline (speedup 1.0000x reference)
#include <cuda_runtime.h>

// Problem dims
#define MB 8
#define TT 4000
#define BBCH 128
#define HH 512
#define MT (MB*TT)      // 32000 rows
#define LP (TT+4)       // padded length for deform conv (pad_tot = 4)
#define TC 32           // t-tile for fused offset+deform kernel
#define RNUM (TC+5)     // 37 smem rows
#define OD_SMEM ((2 * HH + RNUM * HH) * 4)   // 79872 B

#define GPAD 36                        // padded row stride (words) in gemm smem
#define STAGE_W (128 * GPAD)           // words per operand stage (A or B)
#define NSTAGE 4
#define GSMEM_BYTES (2 * NSTAGE * STAGE_W * 4)   // 147456 B

// ---- scratch (device globals; no allocations allowed) ----
__device__ float g_h[MT * HH];      // prelu(x@W1^T), pre-norm   [M*T, H]
__device__ float g_p[MT * HH];      // prelu2(deform out), pre-norm
__device__ float g_wg[BBCH * HH];   // pw_w * norm2_g (folded weights)
__device__ float g_S[BBCH], g_C0[BBCH];
__device__ float g_sum1[MB], g_sq1[MB], g_sum2[MB], g_sq2[MB];

// ---- tf32 mma helpers (raw fp32 operands; HW truncates to tf32) ----
__device__ __forceinline__ void mma_tf32(float c[4], const unsigned a[4], const unsigned b[2]) {
    asm volatile(
        "mma.sync.aligned.m16n8k8.row.col.f32.tf32.tf32.f32 "
        "{%0,%1,%2,%3}, {%4,%5,%6,%7}, {%8,%9}, {%0,%1,%2,%3};"
        : "+f"(c[0]), "+f"(c[1]), "+f"(c[2]), "+f"(c[3])
        : "r"(a[0]), "r"(a[1]), "r"(a[2]), "r"(a[3]), "r"(b[0]), "r"(b[1]));
}
__device__ __forceinline__ void ldsm_x4(unsigned a[4], unsigned addr) {
    asm volatile("ldmatrix.sync.aligned.m8n8.x4.shared.b16 {%0,%1,%2,%3}, [%4];"
                 : "=r"(a[0]), "=r"(a[1]), "=r"(a[2]), "=r"(a[3]) : "r"(addr));
}
__device__ __forceinline__ void ldsm_x2(unsigned b[2], unsigned addr) {
    asm volatile("ldmatrix.sync.aligned.m8n8.x2.shared.b16 {%0,%1}, [%2];"
                 : "=r"(b[0]), "=r"(b[1]) : "r"(addr));
}
__device__ __forceinline__ void cp16(unsigned dst, const void* src) {
    asm volatile("cp.async.cg.shared.global [%0], [%1], 16;" :: "r"(dst), "l"(src));
}
#define CP_COMMIT() asm volatile("cp.async.commit_group;")
#define CP_WAIT(N)  asm volatile("cp.async.wait_group %0;" :: "n"(N))

// ---------------------------------------------------------------------------
// Precompute folded GEMM2 weights + zero the stat accumulators.
__global__ void wg_kernel(const float* __restrict__ W,     // pw_w [128,512]
                          const float* __restrict__ gam,   // norm2_g
                          const float* __restrict__ bet) { // norm2_b
    const int b = blockIdx.x;
    const int tid = threadIdx.x;   // 128 threads
    if (b == 0 && tid < MB) {
        g_sum1[tid] = 0.f; g_sq1[tid] = 0.f;
        g_sum2[tid] = 0.f; g_sq2[tid] = 0.f;
    }
    __shared__ float rs[128], rc[128];
    float s = 0.f, c0 = 0.f;
    for (int h = tid; h < HH; h += 128) {
        float w = W[(size_t)b * HH + h];
        float wg = w * gam[h];
        g_wg[(size_t)b * HH + h] = wg;
        s += wg;
        c0 += w * bet[h];
    }
    rs[tid] = s; rc[tid] = c0; __syncthreads();
    for (int o = 64; o > 0; o >>= 1) {
        if (tid < o) { rs[tid] += rs[tid + o]; rc[tid] += rc[tid + o]; }
        __syncthreads();
    }
    if (tid == 0) { g_S[b] = rs[0]; g_C0[b] = rc[0]; }
}

// ---------------------------------------------------------------------------
// GEMM1 (tf32): h[row,n] = prelu( sum_k x[row,k]*W1[n,k] ), fused gLN1 stats.
// 128x128 tile, 512 threads / 16 warps (4m x 4n), BK=32, 4-stage cp.async pipeline.
__global__ void __launch_bounds__(512, 1)
gemm1_kernel(const float* __restrict__ A,   // x [32000,128]
             const float* __restrict__ W,   // conv1_w [512,128]
             const float* __restrict__ prelu_a) {
    extern __shared__ float sm[];
    const int tid = threadIdx.x;
    const int lane = tid & 31, warp = tid >> 5;
    const int warpM = warp & 3, warpN = warp >> 2;
    const int gid = lane >> 2, tig = lane & 3;
    const int rowTile = blockIdx.x * 128, colTile = blockIdx.y * 128;

    const int aRow = (lane & 7) + ((lane >> 3) & 1) * 8;
    const int aKq  = (lane >> 4) * 4;
    const int bRow = lane & 7;
    const int bKq  = ((lane >> 3) & 1) * 4;
    const unsigned sBase = (unsigned)__cvta_generic_to_shared(sm);

    const int ldr = tid >> 3, ldq = (tid & 7) * 4;
    const int ldr2 = ldr + 64;

    float c[2][4][4];
#pragma unroll
    for (int mt = 0; mt < 2; mt++)
#pragma unroll
        for (int nt = 0; nt < 4; nt++)
#pragma unroll
            for (int i = 0; i < 4; i++) c[mt][nt][i] = 0.f;

    const int KT = BBCH / 32;   // 4 k-tiles
    // prologue: stages 0..2
#pragma unroll
    for (int p = 0; p < 3; p++) {
        if (p < KT) {
            int k0 = p * 32;
            unsigned ao = sBase + (p * STAGE_W) * 4;
            unsigned bo = sBase + ((NSTAGE + p) * STAGE_W) * 4;
            cp16(ao + (ldr  * GPAD + ldq) * 4, &A[(size_t)(rowTile + ldr ) * BBCH + k0 + ldq]);
            cp16(ao + (ldr2 * GPAD + ldq) * 4, &A[(size_t)(rowTile + ldr2) * BBCH + k0 + ldq]);
            cp16(bo + (ldr  * GPAD + ldq) * 4, &W[(size_t)(colTile + ldr ) * BBCH + k0 + ldq]);
            cp16(bo + (ldr2 * GPAD + ldq) * 4, &W[(size_t)(colTile + ldr2) * BBCH + k0 + ldq]);
        }
        CP_COMMIT();
    }

    for (int kt = 0; kt < KT; kt++) {
        if (kt + 3 < KT) { CP_WAIT(2); } else { CP_WAIT(0); }
        __syncthreads();
        if (kt + 3 < KT) {
            int p = kt + 3, st2 = p & (NSTAGE - 1);
            int k0 = p * 32;
            unsigned ao = sBase + (st2 * STAGE_W) * 4;
            unsigned bo = sBase + ((NSTAGE + st2) * STAGE_W) * 4;
            cp16(ao + (ldr  * GPAD + ldq) * 4, &A[(size_t)(rowTile + ldr ) * BBCH + k0 + ldq]);
            cp16(ao + (ldr2 * GPAD + ldq) * 4, &A[(size_t)(rowTile + ldr2) * BBCH + k0 + ldq]);
            cp16(bo + (ldr  * GPAD + ldq) * 4, &W[(size_t)(colTile + ldr ) * BBCH + k0 + ldq]);
            cp16(bo + (ldr2 * GPAD + ldq) * 4, &W[(size_t)(colTile + ldr2) * BBCH + k0 + ldq]);
            CP_COMMIT();
        }
        const int st = kt & (NSTAGE - 1);
        const unsigned sAs = sBase + (st * STAGE_W) * 4;
        const unsigned sBs = sBase + ((NSTAGE + st) * STAGE_W) * 4;
#pragma unroll
        for (int ks = 0; ks < 4; ks++) {
            unsigned b[4][2];
#pragma unroll
            for (int nt = 0; nt < 4; nt++)
                ldsm_x2(b[nt], sBs + ((warpN * 32 + nt * 8 + bRow) * GPAD + ks * 8 + bKq) * 4);
#pragma unroll
            for (int mt = 0; mt < 2; mt++) {
                unsigned a[4];
                ldsm_x4(a, sAs + ((warpM * 32 + mt * 16 + aRow) * GPAD + ks * 8 + aKq) * 4);
#pragma unroll
                for (int nt = 0; nt < 4; nt++) mma_tf32(c[mt][nt], a, b[nt]);
            }
        }
    }

    // Epilogue: prelu + store + gLN1 stats via warp-shuffle + atomics.
    const float a = prelu_a[0];
    const int m0 = rowTile / TT;
    const int m1 = (rowTile + 127) / TT;
    const int rowB = (m0 + 1) * TT;
    float s[2] = {0.f, 0.f}, q[2] = {0.f, 0.f};
#pragma unroll
    for (int mt = 0; mt < 2; mt++) {
        int r0 = rowTile + warpM * 32 + mt * 16 + gid;
        int bin0 = (r0 >= rowB) ? 1 : 0;
        int bin8 = (r0 + 8 >= rowB) ? 1 : 0;
#pragma unroll
        for (int nt = 0; nt < 4; nt++) {
            int col = colTile + warpN * 32 + nt * 8 + 2 * tig;
            float v0 = c[mt][nt][0]; v0 = v0 >= 0.f ? v0 : a * v0;
            float v1 = c[mt][nt][1]; v1 = v1 >= 0.f ? v1 : a * v1;
            float v2 = c[mt][nt][2]; v2 = v2 >= 0.f ? v2 : a * v2;
            float v3 = c[mt][nt][3]; v3 = v3 >= 0.f ? v3 : a * v3;
            *(float2*)&g_h[(size_t)r0 * HH + col]       = make_float2(v0, v1);
            *(float2*)&g_h[(size_t)(r0 + 8) * HH + col] = make_float2(v2, v3);
            s[bin0] += v0 + v1;        q[bin0] += v0 * v0 + v1 * v1;
            s[bin8] += v2 + v3;        q[bin8] += v2 * v2 + v3 * v3;
        }
    }
#pragma unroll
    for (int o = 16; o > 0; o >>= 1) {
        s[0] += __shfl_down_sync(0xffffffffu, s[0], o);
        q[0] += __shfl_down_sync(0xffffffffu, q[0], o);
        s[1] += __shfl_down_sync(0xffffffffu, s[1], o);
        q[1] += __shfl_down_sync(0xffffffffu, q[1], o);
    }
    if (lane == 0) {
        atomicAdd(&g_sum1[m0], s[0]);
        atomicAdd(&g_sq1[m0],  q[0]);
        if (m1 > m0) {
            atomicAdd(&g_sum1[m0 + 1], s[1]);
            atomicAdd(&g_sq1[m0 + 1],  q[1]);
        }
    }
}

// ---------------------------------------------------------------------------
// Fused offsets + deformable depthwise conv: 32-t tile, 512 threads.
__global__ void __launch_bounds__(512, 2)
offdef_kernel(const float* __restrict__ odww,  // off_dw_w [512,3]
              const float* __restrict__ odc_a,
              const float* __restrict__ opww,  // off_pw_w [3,512]
              const float* __restrict__ opc_a,
              const float* __restrict__ dww,   // dw_w [512,3]
              const float* __restrict__ dwb,   // dw_b [512]
              const float* __restrict__ a2p,   // prelu2_a
              const float* __restrict__ gam,   // norm1_g
              const float* __restrict__ bet) { // norm1_b
    extern __shared__ float osm[];
    float* sgc  = osm;
    float* sbc  = osm + HH;
    float* rows = osm + 2 * HH;
    __shared__ float w0[TC][3], w1[TC][3];
    __shared__ int   i0[TC][3], i1[TC][3];

    const int m  = blockIdx.y;
    const int t0 = blockIdx.x * TC;
    const int tid = threadIdx.x;
    const float nrm = (float)TT * (float)HH;
    const float mu = g_sum1[m] / nrm;
    const float iv = 1.0f / sqrtf(g_sq1[m] / nrm - mu * mu + 1e-8f);

    for (int c = tid; c < HH; c += 512) {
        float gc = gam[c] * iv;
        sgc[c] = gc;
        sbc[c] = bet[c] - gc * mu;
    }
    __syncthreads();

    const float* base = g_h + (size_t)m * TT * HH;
    for (int e = tid; e < RNUM * (HH / 4); e += 512) {
        int j = e >> 7, c4 = e & 127;
        int src = t0 - 2 + j;
        if (src < 0) src = -src;
        if (src >= TT) src = 2 * TT - 2 - src;
        float4 v = *(const float4*)(base + (size_t)src * HH + c4 * 4);
        float4 g4 = *(const float4*)(sgc + c4 * 4);
        float4 b4 = *(const float4*)(sbc + c4 * 4);
        float4 r;
        r.x = g4.x * v.x + b4.x;
        r.y = g4.y * v.y + b4.y;
        r.z = g4.z * v.z + b4.z;
        r.w = g4.w * v.w + b4.w;
        *(float4*)(rows + j * HH + c4 * 4) = r;
    }
    __syncthreads();

    // Phase 1: offsets (16 threads per t, 32 t), float4 over channels.
    {
        const int tyy = tid >> 4, txx = tid & 15;
        const int t = t0 + tyy;
        const float* r0 = rows + (tyy + 1) * HH;
        const float* r1 = rows + (tyy + 2) * HH;
        const float* r2 = rows + (tyy + 3) * HH;
        const float aodc = odc_a[0];
        float s0 = 0.f, s1 = 0.f, s2 = 0.f;
#pragma unroll
        for (int it = 0; it < 8; it++) {
            int c = (txx + it * 16) * 4;
            float4 v0 = *(const float4*)(r0 + c);
            float4 v1 = *(const float4*)(r1 + c);
            float4 v2 = *(const float4*)(r2 + c);
            float4 f0 = *(const float4*)(odww + c * 3);
            float4 f1 = *(const float4*)(odww + c * 3 + 4);
            float4 f2 = *(const float4*)(odww + c * 3 + 8);
            float4 p0 = *(const float4*)(opww + c);
            float4 p1 = *(const float4*)(opww + HH + c);
            float4 p2 = *(const float4*)(opww + 2 * HH + c);
            float od;
            od = f0.x * v0.x + f0.y * v1.x + f0.z * v2.x;
            od = od >= 0.f ? od : aodc * od;
            s0 += p0.x * od; s1 += p1.x * od; s2 += p2.x * od;
            od = f0.w * v0.y + f1.x * v1.y + f1.y * v2.y;
            od = od >= 0.f ? od : aodc * od;
            s0 += p0.y * od; s1 += p1.y * od; s2 += p2.y * od;
            od = f1.z * v0.z + f1.w * v1.z + f2.x * v2.z;
            od = od >= 0.f ? od : aodc * od;
            s0 += p0.z * od; s1 += p1.z * od; s2 += p2.z * od;
            od = f2.y * v0.w + f2.z * v1.w + f2.w * v2.w;
            od = od >= 0.f ? od : aodc * od;
            s0 += p0.w * od; s1 += p1.w * od; s2 += p2.w * od;
        }
#pragma unroll
        for (int o = 8; o > 0; o >>= 1) {
            s0 += __shfl_down_sync(0xffffffffu, s0, o, 16);
            s1 += __shfl_down_sync(0xffffffffu, s1, o, 16);
            s2 += __shfl_down_sync(0xffffffffu, s2, o, 16);
        }
        if (txx == 0) {
            const float aopc = opc_a[0];
            float off[3];
            off[0] = s0 >= 0.f ? s0 : aopc * s0;
            off[1] = s1 >= 0.f ? s1 : aopc * s1;
            off[2] = s2 >= 0.f ? s2 : aopc * s2;
#pragma unroll
            for (int k = 0; k < 3; k++) {
                float tpos = (float)t + 2.0f * (float)k + off[k];
                tpos = fminf(fmaxf(tpos, (float)t), (float)(t + 4));
                int U = (int)floorf(tpos);
                U = min(U, LP - 2);
                float Uf = (float)U;
                w0[tyy][k] = fmaxf(1.0f - fabsf(Uf - tpos), 0.0f);
                w1[tyy][k] = fmaxf(1.0f - fabsf(Uf + 1.0f - tpos), 0.0f);
                i0[tyy][k] = U - t0;
                i1[tyy][k] = U + 1 - t0;
            }
        }
    }
    __syncthreads();

    // Phase 2: deform depthwise conv + bias + PReLU2 + gLN2 stats, float4.
    const float a2 = a2p[0];
    float lsum = 0.f, lsq = 0.f;
    for (int e = tid; e < TC * (HH / 4); e += 512) {
        int tyy = e >> 7, c = (e & 127) * 4;
        float4 f0 = *(const float4*)(dww + c * 3);
        float4 f1 = *(const float4*)(dww + c * 3 + 4);
        float4 f2 = *(const float4*)(dww + c * 3 + 8);
        float4 sa[3];
#pragma unroll
        for (int k = 0; k < 3; k++) {
            const float* ra = rows + i0[tyy][k] * HH + c;
            const float* rb = rows + i1[tyy][k] * HH + c;
            float4 va = *(const float4*)ra;
            float4 vb = *(const float4*)rb;
            float wa = w0[tyy][k], wb = w1[tyy][k];
            sa[k].x = wa * va.x + wb * vb.x;
            sa[k].y = wa * va.y + wb * vb.y;
            sa[k].z = wa * va.z + wb * vb.z;
            sa[k].w = wa * va.w + wb * vb.w;
        }
        float4 b4 = *(const float4*)(dwb + c);
        float4 y;
        y.x = b4.x + f0.x * sa[0].x + f0.y * sa[1].x + f0.z * sa[2].x;
        y.y = b4.y + f0.w * sa[0].y + f1.x * sa[1].y + f1.y * sa[2].y;
        y.z = b4.z + f1.z * sa[0].z + f1.w * sa[1].z + f2.x * sa[2].z;
        y.w = b4.w + f2.y * sa[0].w + f2.z * sa[1].w + f2.w * sa[2].w;
        y.x = y.x >= 0.f ? y.x : a2 * y.x;
        y.y = y.y >= 0.f ? y.y : a2 * y.y;
        y.z = y.z >= 0.f ? y.z : a2 * y.z;
        y.w = y.w >= 0.f ? y.w : a2 * y.w;
        *(float4*)(g_p + (size_t)(m * TT + t0 + tyy) * HH + c) = y;
        lsum += y.x + y.y + y.z + y.w;
        lsq  += y.x * y.x + y.y * y.y + y.z * y.z + y.w * y.w;
    }
#pragma unroll
    for (int o = 16; o > 0; o >>= 1) {
        lsum += __shfl_down_sync(0xffffffffu, lsum, o);
        lsq  += __shfl_down_sync(0xffffffffu, lsq, o);
    }
    if ((tid & 31) == 0) {
        atomicAdd(&g_sum2[m], lsum);
        atomicAdd(&g_sq2[m],  lsq);
    }
}

// ---------------------------------------------------------------------------
// GEMM2 (tf32): out[row,b] = x[row,b] + iv2[m]*( (Wg@p)[row,b] - mu2[m]*S[b] ) + C0[b]
// 128x128 tile, 512 threads, 4-stage cp.async pipeline, gLN stats inline.
__global__ void __launch_bounds__(512, 1)
gemm2_kernel(const float* __restrict__ X,    // residual x [32000,128]
             float* __restrict__ out) {
    extern __shared__ float sm[];
    const int tid = threadIdx.x;
    const int lane = tid & 31, warp = tid >> 5;
    const int warpM = warp & 3, warpN = warp >> 2;
    const int gid = lane >> 2, tig = lane & 3;
    const int rowTile = blockIdx.x * 128;

    const int aRow = (lane & 7) + ((lane >> 3) & 1) * 8;
    const int aKq  = (lane >> 4) * 4;
    const int bRow = lane & 7;
    const int bKq  = ((lane >> 3) & 1) * 4;
    const unsigned sBase = (unsigned)__cvta_generic_to_shared(sm);

    const int ldr = tid >> 3, ldq = (tid & 7) * 4;
    const int ldr2 = ldr + 64;

    float c[2][4][4];
#pragma unroll
    for (int mt = 0; mt < 2; mt++)
#pragma unroll
        for (int nt = 0; nt < 4; nt++)
#pragma unroll
            for (int i = 0; i < 4; i++) c[mt][nt][i] = 0.f;

    const int KT = HH / 32;   // 16 k-tiles
#pragma unroll
    for (int p = 0; p < 3; p++) {
        int k0 = p * 32;
        unsigned ao = sBase + (p * STAGE_W) * 4;
        unsigned bo = sBase + ((NSTAGE + p) * STAGE_W) * 4;
        cp16(ao + (ldr  * GPAD + ldq) * 4, &g_p[(size_t)(rowTile + ldr ) * HH + k0 + ldq]);
        cp16(ao + (ldr2 * GPAD + ldq) * 4, &g_p[(size_t)(rowTile + ldr2) * HH + k0 + ldq]);
        cp16(bo + (ldr  * GPAD + ldq) * 4, &g_wg[(size_t)ldr  * HH + k0 + ldq]);
        cp16(bo + (ldr2 * GPAD + ldq) * 4, &g_wg[(size_t)ldr2 * HH + k0 + ldq]);
        CP_COMMIT();
    }

    for (int kt = 0; kt < KT; kt++) {
        if (kt + 3 < KT) { CP_WAIT(2); } else { CP_WAIT(0); }
        __syncthreads();
        if (kt + 3 < KT) {
            int p = kt + 3, st2 = p & (NSTAGE - 1);
            int k0 = p * 32;
            unsigned ao = sBase + (st2 * STAGE_W) * 4;
            unsigned bo = sBase + ((NSTAGE + st2) * STAGE_W) * 4;
            cp16(ao + (ldr  * GPAD + ldq) * 4, &g_p[(size_t)(rowTile + ldr ) * HH + k0 + ldq]);
            cp16(ao + (ldr2 * GPAD + ldq) * 4, &g_p[(size_t)(rowTile + ldr2) * HH + k0 + ldq]);
            cp16(bo + (ldr  * GPAD + ldq) * 4, &g_wg[(size_t)ldr  * HH + k0 + ldq]);
            cp16(bo + (ldr2 * GPAD + ldq) * 4, &g_wg[(size_t)ldr2 * HH + k0 + ldq]);
            CP_COMMIT();
        }
        const int st = kt & (NSTAGE - 1);
        const unsigned sAs = sBase + (st * STAGE_W) * 4;
        const unsigned sBs = sBase + ((NSTAGE + st) * STAGE_W) * 4;
#pragma unroll
        for (int ks = 0; ks < 4; ks++) {
            unsigned b[4][2];
#pragma unroll
            for (int nt = 0; nt < 4; nt++)
                ldsm_x2(b[nt], sBs + ((warpN * 32 + nt * 8 + bRow) * GPAD + ks * 8 + bKq) * 4);
#pragma unroll
            for (int mt = 0; mt < 2; mt++) {
                unsigned a[4];
                ldsm_x4(a, sAs + ((warpM * 32 + mt * 16 + aRow) * GPAD + ks * 8 + aKq) * 4);
#pragma unroll
                for (int nt = 0; nt < 4; nt++) mma_tf32(c[mt][nt], a, b[nt]);
            }
        }
    }

    const int m0 = rowTile / TT;
    const int rowB = (m0 + 1) * TT;
    const float nrm = (float)TT * (float)HH;
#pragma unroll
    for (int mt = 0; mt < 2; mt++) {
        int r0 = rowTile + warpM * 32 + mt * 16 + gid;
        int mmA = (r0 >= rowB) ? m0 + 1 : m0;
        int mmB = (r0 + 8 >= rowB) ? m0 + 1 : m0;
        float muA = g_sum2[mmA] / nrm;
        float ivA = 1.0f / sqrtf(g_sq2[mmA] / nrm - muA * muA + 1e-8f);
        float muB = g_sum2[mmB] / nrm;
        float ivB = 1.0f / sqrtf(g_sq2[mmB] / nrm - muB * muB + 1e-8f);
#pragma unroll
        for (int nt = 0; nt < 4; nt++) {
            int col = warpN * 32 + nt * 8 + 2 * tig;
            float S0 = g_S[col], S1 = g_S[col + 1];
            float C00 = g_C0[col], C01 = g_C0[col + 1];
            float2 x0 = *(const float2*)&X[(size_t)r0 * BBCH + col];
            float2 x8 = *(const float2*)&X[(size_t)(r0 + 8) * BBCH + col];
            *(float2*)&out[(size_t)r0 * BBCH + col] = make_float2(
                ivA * (c[mt][nt][0] - muA * S0) + C00 + x0.x,
                ivA * (c[mt][nt][1] - muA * S1) + C01 + x0.y);
            *(float2*)&out[(size_t)(r0 + 8) * BBCH + col] = make_float2(
                ivB * (c[mt][nt][2] - muB * S0) + C00 + x8.x,
                ivB * (c[mt][nt][3] - muB * S1) + C01 + x8.y);
        }
    }
}

// ---------------------------------------------------------------------------
extern "C" void kernel_launch(void* const* d_in, const int* in_sizes, int n_in,
                              void* d_out, int out_size) {
    (void)in_sizes; (void)n_in; (void)out_size;
    const float* x        = (const float*)d_in[0];
    const float* conv1_w  = (const float*)d_in[1];
    const float* prelu1_a = (const float*)d_in[2];
    const float* norm1_g  = (const float*)d_in[3];
    const float* norm1_b  = (const float*)d_in[4];
    const float* off_dw_w = (const float*)d_in[5];
    const float* odc_a    = (const float*)d_in[6];
    const float* off_pw_w = (const float*)d_in[7];
    const float* opc_a    = (const float*)d_in[8];
    const float* dw_w     = (const float*)d_in[9];
    const float* dw_b     = (const float*)d_in[10];
    const float* prelu2_a = (const float*)d_in[11];
    const float* norm2_g  = (const float*)d_in[12];
    const float* norm2_b  = (const float*)d_in[13];
    const float* pw_w     = (const float*)d_in[14];
    float* out = (float*)d_out;

    cudaFuncSetAttribute(gemm1_kernel, cudaFuncAttributeMaxDynamicSharedMemorySize, GSMEM_BYTES);
    cudaFuncSetAttribute(gemm2_kernel, cudaFuncAttributeMaxDynamicSharedMemorySize, GSMEM_BYTES);
    cudaFuncSetAttribute(offdef_kernel, cudaFuncAttributeMaxDynamicSharedMemorySize, OD_SMEM);

    wg_kernel<<<BBCH, 128>>>(pw_w, norm2_g, norm2_b);
    gemm1_kernel<<<dim3(MT / 128, HH / 128), 512, GSMEM_BYTES>>>(x, conv1_w, prelu1_a);
    offdef_kernel<<<dim3(TT / TC, MB), 512, OD_SMEM>>>(off_dw_w, odc_a, off_pw_w, opc_a,
                                                       dw_w, dw_b, prelu2_a, norm1_g, norm1_b);
    gemm2_kernel<<<MT / 128, 512, GSMEM_BYTES>>>(x, out);
}

// round 13
// speedup vs baseline: 1.0871x; 1.0871x over previous
#include <cuda_runtime.h>

// Problem dims
#define MB 8
#define TT 4000
#define BBCH 128
#define HH 512
#define MT (MB*TT)      // 32000 rows
#define LP (TT+4)       // padded length for deform conv (pad_tot = 4)
#define TC 32           // t-tile for fused offset+deform kernel
#define RNUM (TC+5)     // 37 smem rows
#define OD_SMEM ((2 * HH + RNUM * HH) * 4)   // 79872 B

#define GPAD 36                        // padded row stride (words) in gemm smem
#define STAGE_W (128 * GPAD)           // words per operand stage
#define GSMEM_BYTES (2 * 2 * STAGE_W * 4)   // 2 stages x (A+B) = 73728 B

// ---- scratch (device globals; no allocations allowed) ----
__device__ float g_h[MT * HH];      // prelu(x@W1^T), pre-norm   [M*T, H]
__device__ float g_p[MT * HH];      // prelu2(deform out), pre-norm
__device__ float g_wg[BBCH * HH];   // pw_w * norm2_g (folded weights)
__device__ float g_S[BBCH], g_C0[BBCH];
__device__ float g_sum1[MB], g_sq1[MB], g_sum2[MB], g_sq2[MB];

// ---- tf32 mma helpers (raw fp32 operands; HW truncates to tf32) ----
__device__ __forceinline__ void mma_tf32(float c[4], const unsigned a[4], const unsigned b[2]) {
    asm volatile(
        "mma.sync.aligned.m16n8k8.row.col.f32.tf32.tf32.f32 "
        "{%0,%1,%2,%3}, {%4,%5,%6,%7}, {%8,%9}, {%0,%1,%2,%3};"
        : "+f"(c[0]), "+f"(c[1]), "+f"(c[2]), "+f"(c[3])
        : "r"(a[0]), "r"(a[1]), "r"(a[2]), "r"(a[3]), "r"(b[0]), "r"(b[1]));
}
__device__ __forceinline__ void ldsm_x4(unsigned a[4], unsigned addr) {
    asm volatile("ldmatrix.sync.aligned.m8n8.x4.shared.b16 {%0,%1,%2,%3}, [%4];"
                 : "=r"(a[0]), "=r"(a[1]), "=r"(a[2]), "=r"(a[3]) : "r"(addr));
}
__device__ __forceinline__ void ldsm_x2(unsigned b[2], unsigned addr) {
    asm volatile("ldmatrix.sync.aligned.m8n8.x2.shared.b16 {%0,%1}, [%2];"
                 : "=r"(b[0]), "=r"(b[1]) : "r"(addr));
}
__device__ __forceinline__ void cp16(unsigned dst, const void* src) {
    asm volatile("cp.async.cg.shared.global [%0], [%1], 16;" :: "r"(dst), "l"(src));
}
#define CP_COMMIT()  asm volatile("cp.async.commit_group;")
#define CP_WAIT_ALL() asm volatile("cp.async.wait_all;")

// ---------------------------------------------------------------------------
// Precompute folded GEMM2 weights + zero the stat accumulators.
__global__ void wg_kernel(const float* __restrict__ W,     // pw_w [128,512]
                          const float* __restrict__ gam,   // norm2_g
                          const float* __restrict__ bet) { // norm2_b
    const int b = blockIdx.x;
    const int tid = threadIdx.x;   // 128 threads
    if (b == 0 && tid < MB) {
        g_sum1[tid] = 0.f; g_sq1[tid] = 0.f;
        g_sum2[tid] = 0.f; g_sq2[tid] = 0.f;
    }
    __shared__ float rs[128], rc[128];
    float s = 0.f, c0 = 0.f;
    for (int h = tid; h < HH; h += 128) {
        float w = W[(size_t)b * HH + h];
        float wg = w * gam[h];
        g_wg[(size_t)b * HH + h] = wg;
        s += wg;
        c0 += w * bet[h];
    }
    rs[tid] = s; rc[tid] = c0; __syncthreads();
    for (int o = 64; o > 0; o >>= 1) {
        if (tid < o) { rs[tid] += rs[tid + o]; rc[tid] += rc[tid + o]; }
        __syncthreads();
    }
    if (tid == 0) { g_S[b] = rs[0]; g_C0[b] = rc[0]; }
}

// ---------------------------------------------------------------------------
// GEMM1 (tf32): h[row,n] = prelu( sum_k x[row,k]*W1[n,k] ), fused gLN1 stats.
// 128x128 tile, 512 threads / 16 warps (4m x 4n), BK=32, double-buffered smem.
__global__ void __launch_bounds__(512, 1)
gemm1_kernel(const float* __restrict__ A,   // x [32000,128]
             const float* __restrict__ W,   // conv1_w [512,128]
             const float* __restrict__ prelu_a) {
    extern __shared__ float sm[];
    float* Abuf = sm;
    float* Bbuf = sm + 2 * STAGE_W;
    const int tid = threadIdx.x;
    const int lane = tid & 31, warp = tid >> 5;
    const int warpM = warp & 3, warpN = warp >> 2;
    const int gid = lane >> 2, tig = lane & 3;
    const int rowTile = blockIdx.x * 128, colTile = blockIdx.y * 128;

    const int aRow = (lane & 7) + ((lane >> 3) & 1) * 8;
    const int aKq  = (lane >> 4) * 4;
    const int bRow = lane & 7;
    const int bKq  = ((lane >> 3) & 1) * 4;
    const unsigned sA = (unsigned)__cvta_generic_to_shared(Abuf);
    const unsigned sB = (unsigned)__cvta_generic_to_shared(Bbuf);

    float c[2][4][4];
#pragma unroll
    for (int mt = 0; mt < 2; mt++)
#pragma unroll
        for (int nt = 0; nt < 4; nt++)
#pragma unroll
            for (int i = 0; i < 4; i++) c[mt][nt][i] = 0.f;

    const int ldr = tid >> 3, ldq = (tid & 7) * 4;
    const int ldr2 = ldr + 64;
    {
        *(float4*)&Abuf[ldr  * GPAD + ldq] = *(const float4*)&A[(size_t)(rowTile + ldr ) * BBCH + ldq];
        *(float4*)&Abuf[ldr2 * GPAD + ldq] = *(const float4*)&A[(size_t)(rowTile + ldr2) * BBCH + ldq];
        *(float4*)&Bbuf[ldr  * GPAD + ldq] = *(const float4*)&W[(size_t)(colTile + ldr ) * BBCH + ldq];
        *(float4*)&Bbuf[ldr2 * GPAD + ldq] = *(const float4*)&W[(size_t)(colTile + ldr2) * BBCH + ldq];
    }
    __syncthreads();

    int st = 0;
    for (int k0 = 0; k0 < BBCH; k0 += 32) {
        const bool hn = (k0 + 32) < BBCH;
        float4 fa0, fa1, fb0, fb1;
        if (hn) {
            fa0 = *(const float4*)&A[(size_t)(rowTile + ldr ) * BBCH + k0 + 32 + ldq];
            fa1 = *(const float4*)&A[(size_t)(rowTile + ldr2) * BBCH + k0 + 32 + ldq];
            fb0 = *(const float4*)&W[(size_t)(colTile + ldr ) * BBCH + k0 + 32 + ldq];
            fb1 = *(const float4*)&W[(size_t)(colTile + ldr2) * BBCH + k0 + 32 + ldq];
        }
        const unsigned sAs = sA + st * STAGE_W * 4;
        const unsigned sBs = sB + st * STAGE_W * 4;
#pragma unroll
        for (int ks = 0; ks < 4; ks++) {
            unsigned b[4][2];
#pragma unroll
            for (int nt = 0; nt < 4; nt++)
                ldsm_x2(b[nt], sBs + ((warpN * 32 + nt * 8 + bRow) * GPAD + ks * 8 + bKq) * 4);
#pragma unroll
            for (int mt = 0; mt < 2; mt++) {
                unsigned a[4];
                ldsm_x4(a, sAs + ((warpM * 32 + mt * 16 + aRow) * GPAD + ks * 8 + aKq) * 4);
#pragma unroll
                for (int nt = 0; nt < 4; nt++) mma_tf32(c[mt][nt], a, b[nt]);
            }
        }
        if (hn) {
            float* An = Abuf + (st ^ 1) * STAGE_W;
            float* Bn = Bbuf + (st ^ 1) * STAGE_W;
            *(float4*)&An[ldr  * GPAD + ldq] = fa0;
            *(float4*)&An[ldr2 * GPAD + ldq] = fa1;
            *(float4*)&Bn[ldr  * GPAD + ldq] = fb0;
            *(float4*)&Bn[ldr2 * GPAD + ldq] = fb1;
            __syncthreads();
            st ^= 1;
        }
    }

    // Epilogue: prelu + store + gLN1 stats via warp-shuffle + atomics.
    const float a = prelu_a[0];
    const int m0 = rowTile / TT;
    const int m1 = (rowTile + 127) / TT;
    const int rowB = (m0 + 1) * TT;
    float s[2] = {0.f, 0.f}, q[2] = {0.f, 0.f};
#pragma unroll
    for (int mt = 0; mt < 2; mt++) {
        int r0 = rowTile + warpM * 32 + mt * 16 + gid;
        int bin0 = (r0 >= rowB) ? 1 : 0;
        int bin8 = (r0 + 8 >= rowB) ? 1 : 0;
#pragma unroll
        for (int nt = 0; nt < 4; nt++) {
            int col = colTile + warpN * 32 + nt * 8 + 2 * tig;
            float v0 = c[mt][nt][0]; v0 = v0 >= 0.f ? v0 : a * v0;
            float v1 = c[mt][nt][1]; v1 = v1 >= 0.f ? v1 : a * v1;
            float v2 = c[mt][nt][2]; v2 = v2 >= 0.f ? v2 : a * v2;
            float v3 = c[mt][nt][3]; v3 = v3 >= 0.f ? v3 : a * v3;
            *(float2*)&g_h[(size_t)r0 * HH + col]       = make_float2(v0, v1);
            *(float2*)&g_h[(size_t)(r0 + 8) * HH + col] = make_float2(v2, v3);
            s[bin0] += v0 + v1;        q[bin0] += v0 * v0 + v1 * v1;
            s[bin8] += v2 + v3;        q[bin8] += v2 * v2 + v3 * v3;
        }
    }
#pragma unroll
    for (int o = 16; o > 0; o >>= 1) {
        s[0] += __shfl_down_sync(0xffffffffu, s[0], o);
        q[0] += __shfl_down_sync(0xffffffffu, q[0], o);
        s[1] += __shfl_down_sync(0xffffffffu, s[1], o);
        q[1] += __shfl_down_sync(0xffffffffu, q[1], o);
    }
    if (lane == 0) {
        atomicAdd(&g_sum1[m0], s[0]);
        atomicAdd(&g_sq1[m0],  q[0]);
        if (m1 > m0) {
            atomicAdd(&g_sum1[m0 + 1], s[1]);
            atomicAdd(&g_sq1[m0 + 1],  q[1]);
        }
    }
}

// ---------------------------------------------------------------------------
// Fused offsets + deformable depthwise conv: 32-t tile, 512 threads.
// RAW rows staged via cp.async; gLN fold applied at consumption (g0+g1==1).
__global__ void __launch_bounds__(512, 2)
offdef_kernel(const float* __restrict__ odww,  // off_dw_w [512,3]
              const float* __restrict__ odc_a,
              const float* __restrict__ opww,  // off_pw_w [3,512]
              const float* __restrict__ opc_a,
              const float* __restrict__ dww,   // dw_w [512,3]
              const float* __restrict__ dwb,   // dw_b [512]
              const float* __restrict__ a2p,   // prelu2_a
              const float* __restrict__ gam,   // norm1_g
              const float* __restrict__ bet) { // norm1_b
    extern __shared__ float osm[];
    float* sgc  = osm;              // [HH] gc = gam*iv
    float* sbc  = osm + HH;         // [HH] bc = bet - gc*mu
    float* rows = osm + 2 * HH;     // [RNUM * HH] RAW g_h rows
    __shared__ float w0[TC][3], w1[TC][3];
    __shared__ int   i0[TC][3], i1[TC][3];

    const int m  = blockIdx.y;
    const int t0 = blockIdx.x * TC;
    const int tid = threadIdx.x;
    const float nrm = (float)TT * (float)HH;
    const float mu = g_sum1[m] / nrm;
    const float iv = 1.0f / sqrtf(g_sq1[m] / nrm - mu * mu + 1e-8f);

    // Fire-and-forget raw staging (reflect-mapped) — overlaps sgc/sbc build.
    const float* base = g_h + (size_t)m * TT * HH;
    const unsigned sRows = (unsigned)__cvta_generic_to_shared(rows);
    for (int e = tid; e < RNUM * (HH / 4); e += 512) {
        int j = e >> 7, c4 = e & 127;
        int src = t0 - 2 + j;
        if (src < 0) src = -src;
        if (src >= TT) src = 2 * TT - 2 - src;
        cp16(sRows + (j * HH + c4 * 4) * 4, base + (size_t)src * HH + c4 * 4);
    }
    CP_COMMIT();

    for (int c = tid; c < HH; c += 512) {
        float gc = gam[c] * iv;
        sgc[c] = gc;
        sbc[c] = bet[c] - gc * mu;
    }
    CP_WAIT_ALL();
    __syncthreads();

    // Phase 1: offsets (16 threads per t, 32 t). Raw rows; fold gc/bc here:
    //   od = gc*(f0 v0 + f1 v1 + f2 v2) + (f0+f1+f2)*bc
    {
        const int tyy = tid >> 4, txx = tid & 15;
        const int t = t0 + tyy;
        const float* r0 = rows + (tyy + 1) * HH;
        const float* r1 = rows + (tyy + 2) * HH;
        const float* r2 = rows + (tyy + 3) * HH;
        const float aodc = odc_a[0];
        float s0 = 0.f, s1 = 0.f, s2 = 0.f;
#pragma unroll
        for (int it = 0; it < 8; it++) {
            int c = (txx + it * 16) * 4;
            float4 v0 = *(const float4*)(r0 + c);
            float4 v1 = *(const float4*)(r1 + c);
            float4 v2 = *(const float4*)(r2 + c);
            float4 f0 = *(const float4*)(odww + c * 3);
            float4 f1 = *(const float4*)(odww + c * 3 + 4);
            float4 f2 = *(const float4*)(odww + c * 3 + 8);
            float4 p0 = *(const float4*)(opww + c);
            float4 p1 = *(const float4*)(opww + HH + c);
            float4 p2 = *(const float4*)(opww + 2 * HH + c);
            float4 g4 = *(const float4*)(sgc + c);
            float4 b4 = *(const float4*)(sbc + c);
            float od;
            od = g4.x * (f0.x * v0.x + f0.y * v1.x + f0.z * v2.x) + (f0.x + f0.y + f0.z) * b4.x;
            od = od >= 0.f ? od : aodc * od;
            s0 += p0.x * od; s1 += p1.x * od; s2 += p2.x * od;
            od = g4.y * (f0.w * v0.y + f1.x * v1.y + f1.y * v2.y) + (f0.w + f1.x + f1.y) * b4.y;
            od = od >= 0.f ? od : aodc * od;
            s0 += p0.y * od; s1 += p1.y * od; s2 += p2.y * od;
            od = g4.z * (f1.z * v0.z + f1.w * v1.z + f2.x * v2.z) + (f1.z + f1.w + f2.x) * b4.z;
            od = od >= 0.f ? od : aodc * od;
            s0 += p0.z * od; s1 += p1.z * od; s2 += p2.z * od;
            od = g4.w * (f2.y * v0.w + f2.z * v1.w + f2.w * v2.w) + (f2.y + f2.z + f2.w) * b4.w;
            od = od >= 0.f ? od : aodc * od;
            s0 += p0.w * od; s1 += p1.w * od; s2 += p2.w * od;
        }
#pragma unroll
        for (int o = 8; o > 0; o >>= 1) {
            s0 += __shfl_down_sync(0xffffffffu, s0, o, 16);
            s1 += __shfl_down_sync(0xffffffffu, s1, o, 16);
            s2 += __shfl_down_sync(0xffffffffu, s2, o, 16);
        }
        if (txx == 0) {
            const float aopc = opc_a[0];
            float off[3];
            off[0] = s0 >= 0.f ? s0 : aopc * s0;
            off[1] = s1 >= 0.f ? s1 : aopc * s1;
            off[2] = s2 >= 0.f ? s2 : aopc * s2;
#pragma unroll
            for (int k = 0; k < 3; k++) {
                float tpos = (float)t + 2.0f * (float)k + off[k];
                tpos = fminf(fmaxf(tpos, (float)t), (float)(t + 4));
                int U = (int)floorf(tpos);
                U = min(U, LP - 2);
                float Uf = (float)U;
                w0[tyy][k] = fmaxf(1.0f - fabsf(Uf - tpos), 0.0f);
                w1[tyy][k] = fmaxf(1.0f - fabsf(Uf + 1.0f - tpos), 0.0f);
                i0[tyy][k] = U - t0;
                i1[tyy][k] = U + 1 - t0;
            }
        }
    }
    __syncthreads();

    // Phase 2: deform conv on raw rows; fold gc/bc:
    //   s_k = w0 v0 + w1 v1  (raw; since w0+w1 == 1, hn-sample = gc*s_k + bc)
    //   y = dwb + gc*(Σ dww_k s_k) + bc*(Σ dww_k)
    const float a2 = a2p[0];
    float lsum = 0.f, lsq = 0.f;
    for (int e = tid; e < TC * (HH / 4); e += 512) {
        int tyy = e >> 7, c = (e & 127) * 4;
        float4 f0 = *(const float4*)(dww + c * 3);
        float4 f1 = *(const float4*)(dww + c * 3 + 4);
        float4 f2 = *(const float4*)(dww + c * 3 + 8);
        float4 sa[3];
#pragma unroll
        for (int k = 0; k < 3; k++) {
            const float* ra = rows + i0[tyy][k] * HH + c;
            const float* rb = rows + i1[tyy][k] * HH + c;
            float4 va = *(const float4*)ra;
            float4 vb = *(const float4*)rb;
            float wa = w0[tyy][k], wb = w1[tyy][k];
            sa[k].x = wa * va.x + wb * vb.x;
            sa[k].y = wa * va.y + wb * vb.y;
            sa[k].z = wa * va.z + wb * vb.z;
            sa[k].w = wa * va.w + wb * vb.w;
        }
        float4 b4 = *(const float4*)(dwb + c);
        float4 g4 = *(const float4*)(sgc + c);
        float4 bc4 = *(const float4*)(sbc + c);
        float4 y;
        y.x = b4.x + g4.x * (f0.x * sa[0].x + f0.y * sa[1].x + f0.z * sa[2].x)
                   + bc4.x * (f0.x + f0.y + f0.z);
        y.y = b4.y + g4.y * (f0.w * sa[0].y + f1.x * sa[1].y + f1.y * sa[2].y)
                   + bc4.y * (f0.w + f1.x + f1.y);
        y.z = b4.z + g4.z * (f1.z * sa[0].z + f1.w * sa[1].z + f2.x * sa[2].z)
                   + bc4.z * (f1.z + f1.w + f2.x);
        y.w = b4.w + g4.w * (f2.y * sa[0].w + f2.z * sa[1].w + f2.w * sa[2].w)
                   + bc4.w * (f2.y + f2.z + f2.w);
        y.x = y.x >= 0.f ? y.x : a2 * y.x;
        y.y = y.y >= 0.f ? y.y : a2 * y.y;
        y.z = y.z >= 0.f ? y.z : a2 * y.z;
        y.w = y.w >= 0.f ? y.w : a2 * y.w;
        *(float4*)(g_p + (size_t)(m * TT + t0 + tyy) * HH + c) = y;
        lsum += y.x + y.y + y.z + y.w;
        lsq  += y.x * y.x + y.y * y.y + y.z * y.z + y.w * y.w;
    }
#pragma unroll
    for (int o = 16; o > 0; o >>= 1) {
        lsum += __shfl_down_sync(0xffffffffu, lsum, o);
        lsq  += __shfl_down_sync(0xffffffffu, lsq, o);
    }
    if ((tid & 31) == 0) {
        atomicAdd(&g_sum2[m], lsum);
        atomicAdd(&g_sq2[m],  lsq);
    }
}

// ---------------------------------------------------------------------------
// GEMM2 (tf32): out[row,b] = x[row,b] + iv2[m]*( (Wg@p)[row,b] - mu2[m]*S[b] ) + C0[b]
// 128x128 tile, 512 threads, double-buffered smem, gLN stats inline.
__global__ void __launch_bounds__(512, 1)
gemm2_kernel(const float* __restrict__ X,    // residual x [32000,128]
             float* __restrict__ out) {
    extern __shared__ float sm[];
    float* Abuf = sm;
    float* Bbuf = sm + 2 * STAGE_W;
    const int tid = threadIdx.x;
    const int lane = tid & 31, warp = tid >> 5;
    const int warpM = warp & 3, warpN = warp >> 2;
    const int gid = lane >> 2, tig = lane & 3;
    const int rowTile = blockIdx.x * 128;

    const int aRow = (lane & 7) + ((lane >> 3) & 1) * 8;
    const int aKq  = (lane >> 4) * 4;
    const int bRow = lane & 7;
    const int bKq  = ((lane >> 3) & 1) * 4;
    const unsigned sA = (unsigned)__cvta_generic_to_shared(Abuf);
    const unsigned sB = (unsigned)__cvta_generic_to_shared(Bbuf);

    float c[2][4][4];
#pragma unroll
    for (int mt = 0; mt < 2; mt++)
#pragma unroll
        for (int nt = 0; nt < 4; nt++)
#pragma unroll
            for (int i = 0; i < 4; i++) c[mt][nt][i] = 0.f;

    const int ldr = tid >> 3, ldq = (tid & 7) * 4;
    const int ldr2 = ldr + 64;
    {
        *(float4*)&Abuf[ldr  * GPAD + ldq] = *(const float4*)&g_p[(size_t)(rowTile + ldr ) * HH + ldq];
        *(float4*)&Abuf[ldr2 * GPAD + ldq] = *(const float4*)&g_p[(size_t)(rowTile + ldr2) * HH + ldq];
        *(float4*)&Bbuf[ldr  * GPAD + ldq] = *(const float4*)&g_wg[(size_t)ldr  * HH + ldq];
        *(float4*)&Bbuf[ldr2 * GPAD + ldq] = *(const float4*)&g_wg[(size_t)ldr2 * HH + ldq];
    }
    __syncthreads();

    int st = 0;
    for (int k0 = 0; k0 < HH; k0 += 32) {
        const bool hn = (k0 + 32) < HH;
        float4 fa0, fa1, fb0, fb1;
        if (hn) {
            fa0 = *(const float4*)&g_p[(size_t)(rowTile + ldr ) * HH + k0 + 32 + ldq];
            fa1 = *(const float4*)&g_p[(size_t)(rowTile + ldr2) * HH + k0 + 32 + ldq];
            fb0 = *(const float4*)&g_wg[(size_t)ldr  * HH + k0 + 32 + ldq];
            fb1 = *(const float4*)&g_wg[(size_t)ldr2 * HH + k0 + 32 + ldq];
        }
        const unsigned sAs = sA + st * STAGE_W * 4;
        const unsigned sBs = sB + st * STAGE_W * 4;
#pragma unroll
        for (int ks = 0; ks < 4; ks++) {
            unsigned b[4][2];
#pragma unroll
            for (int nt = 0; nt < 4; nt++)
                ldsm_x2(b[nt], sBs + ((warpN * 32 + nt * 8 + bRow) * GPAD + ks * 8 + bKq) * 4);
#pragma unroll
            for (int mt = 0; mt < 2; mt++) {
                unsigned a[4];
                ldsm_x4(a, sAs + ((warpM * 32 + mt * 16 + aRow) * GPAD + ks * 8 + aKq) * 4);
#pragma unroll
                for (int nt = 0; nt < 4; nt++) mma_tf32(c[mt][nt], a, b[nt]);
            }
        }
        if (hn) {
            float* An = Abuf + (st ^ 1) * STAGE_W;
            float* Bn = Bbuf + (st ^ 1) * STAGE_W;
            *(float4*)&An[ldr  * GPAD + ldq] = fa0;
            *(float4*)&An[ldr2 * GPAD + ldq] = fa1;
            *(float4*)&Bn[ldr  * GPAD + ldq] = fb0;
            *(float4*)&Bn[ldr2 * GPAD + ldq] = fb1;
            __syncthreads();
            st ^= 1;
        }
    }

    const int m0 = rowTile / TT;
    const int rowB = (m0 + 1) * TT;
    const float nrm = (float)TT * (float)HH;
#pragma unroll
    for (int mt = 0; mt < 2; mt++) {
        int r0 = rowTile + warpM * 32 + mt * 16 + gid;
        int mmA = (r0 >= rowB) ? m0 + 1 : m0;
        int mmB = (r0 + 8 >= rowB) ? m0 + 1 : m0;
        float muA = g_sum2[mmA] / nrm;
        float ivA = 1.0f / sqrtf(g_sq2[mmA] / nrm - muA * muA + 1e-8f);
        float muB = g_sum2[mmB] / nrm;
        float ivB = 1.0f / sqrtf(g_sq2[mmB] / nrm - muB * muB + 1e-8f);
#pragma unroll
        for (int nt = 0; nt < 4; nt++) {
            int col = warpN * 32 + nt * 8 + 2 * tig;
            float S0 = g_S[col], S1 = g_S[col + 1];
            float C00 = g_C0[col], C01 = g_C0[col + 1];
            float2 x0 = *(const float2*)&X[(size_t)r0 * BBCH + col];
            float2 x8 = *(const float2*)&X[(size_t)(r0 + 8) * BBCH + col];
            *(float2*)&out[(size_t)r0 * BBCH + col] = make_float2(
                ivA * (c[mt][nt][0] - muA * S0) + C00 + x0.x,
                ivA * (c[mt][nt][1] - muA * S1) + C01 + x0.y);
            *(float2*)&out[(size_t)(r0 + 8) * BBCH + col] = make_float2(
                ivB * (c[mt][nt][2] - muB * S0) + C00 + x8.x,
                ivB * (c[mt][nt][3] - muB * S1) + C01 + x8.y);
        }
    }
}

// ---------------------------------------------------------------------------
extern "C" void kernel_launch(void* const* d_in, const int* in_sizes, int n_in,
                              void* d_out, int out_size) {
    (void)in_sizes; (void)n_in; (void)out_size;
    const float* x        = (const float*)d_in[0];
    const float* conv1_w  = (const float*)d_in[1];
    const float* prelu1_a = (const float*)d_in[2];
    const float* norm1_g  = (const float*)d_in[3];
    const float* norm1_b  = (const float*)d_in[4];
    const float* off_dw_w = (const float*)d_in[5];
    const float* odc_a    = (const float*)d_in[6];
    const float* off_pw_w = (const float*)d_in[7];
    const float* opc_a    = (const float*)d_in[8];
    const float* dw_w     = (const float*)d_in[9];
    const float* dw_b     = (const float*)d_in[10];
    const float* prelu2_a = (const float*)d_in[11];
    const float* norm2_g  = (const float*)d_in[12];
    const float* norm2_b  = (const float*)d_in[13];
    const float* pw_w     = (const float*)d_in[14];
    float* out = (float*)d_out;

    cudaFuncSetAttribute(gemm1_kernel, cudaFuncAttributeMaxDynamicSharedMemorySize, GSMEM_BYTES);
    cudaFuncSetAttribute(gemm2_kernel, cudaFuncAttributeMaxDynamicSharedMemorySize, GSMEM_BYTES);
    cudaFuncSetAttribute(offdef_kernel, cudaFuncAttributeMaxDynamicSharedMemorySize, OD_SMEM);

    wg_kernel<<<BBCH, 128>>>(pw_w, norm2_g, norm2_b);
    gemm1_kernel<<<dim3(MT / 128, HH / 128), 512, GSMEM_BYTES>>>(x, conv1_w, prelu1_a);
    offdef_kernel<<<dim3(TT / TC, MB), 512, OD_SMEM>>>(off_dw_w, odc_a, off_pw_w, opc_a,
                                                       dw_w, dw_b, prelu2_a, norm1_g, norm1_b);
    gemm2_kernel<<<MT / 128, 512, GSMEM_BYTES>>>(x, out);
}

// round 14
// speedup vs baseline: 1.1194x; 1.0297x over previous
#include <cuda_runtime.h>

// Problem dims
#define MB 8
#define TT 4000
#define BBCH 128
#define HH 512
#define MT (MB*TT)      // 32000 rows
#define LP (TT+4)       // padded length for deform conv (pad_tot = 4)
#define TC 32           // t-tile for fused offset+deform kernel
#define RNUM (TC+5)     // 37 smem rows
#define OD_SMEM ((2 * HH + RNUM * HH) * 4)   // 79872 B

#define GP64 68                         // padded row stride (words), BK=64
#define STG64 (128 * GP64)              // words per operand stage
#define GSMEM_BYTES (2 * 2 * STG64 * 4) // 2 stages x (A+B) = 139264 B

// ---- scratch (device globals; no allocations allowed) ----
__device__ float g_h[MT * HH];      // prelu(x@W1^T), pre-norm   [M*T, H]
__device__ float g_p[MT * HH];      // prelu2(deform out), pre-norm
__device__ float g_wg[BBCH * HH];   // pw_w * norm2_g (folded weights)
__device__ float g_S[BBCH], g_C0[BBCH];
__device__ float g_sum1[MB], g_sq1[MB], g_sum2[MB], g_sq2[MB];

// ---- tf32 mma helpers (raw fp32 operands; HW truncates to tf32) ----
__device__ __forceinline__ void mma_tf32(float c[4], const unsigned a[4], const unsigned b[2]) {
    asm volatile(
        "mma.sync.aligned.m16n8k8.row.col.f32.tf32.tf32.f32 "
        "{%0,%1,%2,%3}, {%4,%5,%6,%7}, {%8,%9}, {%0,%1,%2,%3};"
        : "+f"(c[0]), "+f"(c[1]), "+f"(c[2]), "+f"(c[3])
        : "r"(a[0]), "r"(a[1]), "r"(a[2]), "r"(a[3]), "r"(b[0]), "r"(b[1]));
}
__device__ __forceinline__ void ldsm_x4(unsigned a[4], unsigned addr) {
    asm volatile("ldmatrix.sync.aligned.m8n8.x4.shared.b16 {%0,%1,%2,%3}, [%4];"
                 : "=r"(a[0]), "=r"(a[1]), "=r"(a[2]), "=r"(a[3]) : "r"(addr));
}
__device__ __forceinline__ void cp16(unsigned dst, const void* src) {
    asm volatile("cp.async.cg.shared.global [%0], [%1], 16;" :: "r"(dst), "l"(src));
}
#define CP_COMMIT()  asm volatile("cp.async.commit_group;")
#define CP_WAIT_ALL() asm volatile("cp.async.wait_all;")

// ---------------------------------------------------------------------------
// Precompute folded GEMM2 weights + zero the stat accumulators.
__global__ void wg_kernel(const float* __restrict__ W,     // pw_w [128,512]
                          const float* __restrict__ gam,   // norm2_g
                          const float* __restrict__ bet) { // norm2_b
    const int b = blockIdx.x;
    const int tid = threadIdx.x;   // 128 threads
    if (b == 0 && tid < MB) {
        g_sum1[tid] = 0.f; g_sq1[tid] = 0.f;
        g_sum2[tid] = 0.f; g_sq2[tid] = 0.f;
    }
    __shared__ float rs[128], rc[128];
    float s = 0.f, c0 = 0.f;
    for (int h = tid; h < HH; h += 128) {
        float w = W[(size_t)b * HH + h];
        float wg = w * gam[h];
        g_wg[(size_t)b * HH + h] = wg;
        s += wg;
        c0 += w * bet[h];
    }
    rs[tid] = s; rc[tid] = c0; __syncthreads();
    for (int o = 64; o > 0; o >>= 1) {
        if (tid < o) { rs[tid] += rs[tid + o]; rc[tid] += rc[tid + o]; }
        __syncthreads();
    }
    if (tid == 0) { g_S[b] = rs[0]; g_C0[b] = rc[0]; }
}

// ---------------------------------------------------------------------------
// Shared GEMM mainloop pieces: 128x128 tile, 512 thr / 16 warps (4m x 4n),
// warp tile 32x32, BK=64, double-buffered, B fragments fetched as x4 pairs.
// Staging: per operand tile 128 rows x 64 words = 2048 float4, 4/thread.

// GEMM1 (tf32): h[row,n] = prelu( sum_k x[row,k]*W1[n,k] ), fused gLN1 stats.
__global__ void __launch_bounds__(512, 1)
gemm1_kernel(const float* __restrict__ A,   // x [32000,128]
             const float* __restrict__ W,   // conv1_w [512,128]
             const float* __restrict__ prelu_a) {
    extern __shared__ float sm[];
    float* Abuf = sm;                 // [2][128][GP64]
    float* Bbuf = sm + 2 * STG64;
    const int tid = threadIdx.x;
    const int lane = tid & 31, warp = tid >> 5;
    const int warpM = warp & 3, warpN = warp >> 2;
    const int gid = lane >> 2, tig = lane & 3;
    const int rowTile = blockIdx.x * 128, colTile = blockIdx.y * 128;

    // A ldsm (x4, one 16-row tile): lanes 0-15 rows, 16-31 k-quad 4..7
    const int aRow = (lane & 7) + ((lane >> 3) & 1) * 8;
    const int aKq  = (lane >> 4) * 4;
    // B pair ldsm (x4, two 8-row tiles): lanes {0-7,8-15} tile0 kq{0,4}, {16-23,24-31} tile1
    const int bRow = lane & 7;
    const int bSel = (lane >> 4) & 1;          // which tile of the pair
    const int bKq  = ((lane >> 3) & 1) * 4;
    const unsigned sA = (unsigned)__cvta_generic_to_shared(Abuf);
    const unsigned sB = (unsigned)__cvta_generic_to_shared(Bbuf);

    float c[2][4][4];
#pragma unroll
    for (int mt = 0; mt < 2; mt++)
#pragma unroll
        for (int nt = 0; nt < 4; nt++)
#pragma unroll
            for (int i = 0; i < 4; i++) c[mt][nt][i] = 0.f;

    const int ldRow = tid >> 4;               // 0..31
    const int ldQ   = (tid & 15) * 4;         // word offset within 64
    // preload k-tile 0 (k = 0..63)
#pragma unroll
    for (int i = 0; i < 4; i++) {
        int r = ldRow + i * 32;
        *(float4*)&Abuf[r * GP64 + ldQ] = *(const float4*)&A[(size_t)(rowTile + r) * BBCH + ldQ];
        *(float4*)&Bbuf[r * GP64 + ldQ] = *(const float4*)&W[(size_t)(colTile + r) * BBCH + ldQ];
    }
    __syncthreads();

    int st = 0;
    for (int kt = 0; kt < 2; kt++) {          // 2 k-tiles of 64
        const bool hn = (kt == 0);
        float4 fa[4], fb[4];
        if (hn) {
#pragma unroll
            for (int i = 0; i < 4; i++) {
                int r = ldRow + i * 32;
                fa[i] = *(const float4*)&A[(size_t)(rowTile + r) * BBCH + 64 + ldQ];
                fb[i] = *(const float4*)&W[(size_t)(colTile + r) * BBCH + 64 + ldQ];
            }
        }
        const unsigned sAs = sA + st * STG64 * 4;
        const unsigned sBs = sB + st * STG64 * 4;
#pragma unroll
        for (int ks = 0; ks < 8; ks++) {
            unsigned b[4][2];
#pragma unroll
            for (int np = 0; np < 2; np++) {   // nt pairs {0,1},{2,3}
                unsigned bp[4];
                ldsm_x4(bp, sBs + ((warpN * 32 + (np * 2 + bSel) * 8 + bRow) * GP64 + ks * 8 + bKq) * 4);
                b[np * 2][0] = bp[0]; b[np * 2][1] = bp[1];
                b[np * 2 + 1][0] = bp[2]; b[np * 2 + 1][1] = bp[3];
            }
#pragma unroll
            for (int mt = 0; mt < 2; mt++) {
                unsigned a[4];
                ldsm_x4(a, sAs + ((warpM * 32 + mt * 16 + aRow) * GP64 + ks * 8 + aKq) * 4);
#pragma unroll
                for (int nt = 0; nt < 4; nt++) mma_tf32(c[mt][nt], a, b[nt]);
            }
        }
        if (hn) {
            float* An = Abuf + (st ^ 1) * STG64;
            float* Bn = Bbuf + (st ^ 1) * STG64;
#pragma unroll
            for (int i = 0; i < 4; i++) {
                int r = ldRow + i * 32;
                *(float4*)&An[r * GP64 + ldQ] = fa[i];
                *(float4*)&Bn[r * GP64 + ldQ] = fb[i];
            }
            __syncthreads();
            st ^= 1;
        }
    }

    // Epilogue: prelu + store + gLN1 stats via warp-shuffle + atomics.
    const float a = prelu_a[0];
    const int m0 = rowTile / TT;
    const int m1 = (rowTile + 127) / TT;
    const int rowB = (m0 + 1) * TT;
    float s[2] = {0.f, 0.f}, q[2] = {0.f, 0.f};
#pragma unroll
    for (int mt = 0; mt < 2; mt++) {
        int r0 = rowTile + warpM * 32 + mt * 16 + gid;
        int bin0 = (r0 >= rowB) ? 1 : 0;
        int bin8 = (r0 + 8 >= rowB) ? 1 : 0;
#pragma unroll
        for (int nt = 0; nt < 4; nt++) {
            int col = colTile + warpN * 32 + nt * 8 + 2 * tig;
            float v0 = c[mt][nt][0]; v0 = v0 >= 0.f ? v0 : a * v0;
            float v1 = c[mt][nt][1]; v1 = v1 >= 0.f ? v1 : a * v1;
            float v2 = c[mt][nt][2]; v2 = v2 >= 0.f ? v2 : a * v2;
            float v3 = c[mt][nt][3]; v3 = v3 >= 0.f ? v3 : a * v3;
            *(float2*)&g_h[(size_t)r0 * HH + col]       = make_float2(v0, v1);
            *(float2*)&g_h[(size_t)(r0 + 8) * HH + col] = make_float2(v2, v3);
            s[bin0] += v0 + v1;        q[bin0] += v0 * v0 + v1 * v1;
            s[bin8] += v2 + v3;        q[bin8] += v2 * v2 + v3 * v3;
        }
    }
#pragma unroll
    for (int o = 16; o > 0; o >>= 1) {
        s[0] += __shfl_down_sync(0xffffffffu, s[0], o);
        q[0] += __shfl_down_sync(0xffffffffu, q[0], o);
        s[1] += __shfl_down_sync(0xffffffffu, s[1], o);
        q[1] += __shfl_down_sync(0xffffffffu, q[1], o);
    }
    const int lane0 = (tid & 31) == 0;
    if (lane0) {
        atomicAdd(&g_sum1[m0], s[0]);
        atomicAdd(&g_sq1[m0],  q[0]);
        if (m1 > m0) {
            atomicAdd(&g_sum1[m0 + 1], s[1]);
            atomicAdd(&g_sq1[m0 + 1],  q[1]);
        }
    }
}

// ---------------------------------------------------------------------------
// Fused offsets + deformable depthwise conv: 32-t tile, 512 threads.
// RAW rows staged via cp.async; gLN fold applied at consumption (g0+g1==1).
__global__ void __launch_bounds__(512, 2)
offdef_kernel(const float* __restrict__ odww,  // off_dw_w [512,3]
              const float* __restrict__ odc_a,
              const float* __restrict__ opww,  // off_pw_w [3,512]
              const float* __restrict__ opc_a,
              const float* __restrict__ dww,   // dw_w [512,3]
              const float* __restrict__ dwb,   // dw_b [512]
              const float* __restrict__ a2p,   // prelu2_a
              const float* __restrict__ gam,   // norm1_g
              const float* __restrict__ bet) { // norm1_b
    extern __shared__ float osm[];
    float* sgc  = osm;
    float* sbc  = osm + HH;
    float* rows = osm + 2 * HH;
    __shared__ float w0[TC][3], w1[TC][3];
    __shared__ int   i0[TC][3], i1[TC][3];

    const int m  = blockIdx.y;
    const int t0 = blockIdx.x * TC;
    const int tid = threadIdx.x;
    const float nrm = (float)TT * (float)HH;
    const float mu = g_sum1[m] / nrm;
    const float iv = 1.0f / sqrtf(g_sq1[m] / nrm - mu * mu + 1e-8f);

    const float* base = g_h + (size_t)m * TT * HH;
    const unsigned sRows = (unsigned)__cvta_generic_to_shared(rows);
    for (int e = tid; e < RNUM * (HH / 4); e += 512) {
        int j = e >> 7, c4 = e & 127;
        int src = t0 - 2 + j;
        if (src < 0) src = -src;
        if (src >= TT) src = 2 * TT - 2 - src;
        cp16(sRows + (j * HH + c4 * 4) * 4, base + (size_t)src * HH + c4 * 4);
    }
    CP_COMMIT();

    for (int c = tid; c < HH; c += 512) {
        float gc = gam[c] * iv;
        sgc[c] = gc;
        sbc[c] = bet[c] - gc * mu;
    }
    CP_WAIT_ALL();
    __syncthreads();

    {
        const int tyy = tid >> 4, txx = tid & 15;
        const int t = t0 + tyy;
        const float* r0 = rows + (tyy + 1) * HH;
        const float* r1 = rows + (tyy + 2) * HH;
        const float* r2 = rows + (tyy + 3) * HH;
        const float aodc = odc_a[0];
        float s0 = 0.f, s1 = 0.f, s2 = 0.f;
#pragma unroll
        for (int it = 0; it < 8; it++) {
            int c = (txx + it * 16) * 4;
            float4 v0 = *(const float4*)(r0 + c);
            float4 v1 = *(const float4*)(r1 + c);
            float4 v2 = *(const float4*)(r2 + c);
            float4 f0 = *(const float4*)(odww + c * 3);
            float4 f1 = *(const float4*)(odww + c * 3 + 4);
            float4 f2 = *(const float4*)(odww + c * 3 + 8);
            float4 p0 = *(const float4*)(opww + c);
            float4 p1 = *(const float4*)(opww + HH + c);
            float4 p2 = *(const float4*)(opww + 2 * HH + c);
            float4 g4 = *(const float4*)(sgc + c);
            float4 b4 = *(const float4*)(sbc + c);
            float od;
            od = g4.x * (f0.x * v0.x + f0.y * v1.x + f0.z * v2.x) + (f0.x + f0.y + f0.z) * b4.x;
            od = od >= 0.f ? od : aodc * od;
            s0 += p0.x * od; s1 += p1.x * od; s2 += p2.x * od;
            od = g4.y * (f0.w * v0.y + f1.x * v1.y + f1.y * v2.y) + (f0.w + f1.x + f1.y) * b4.y;
            od = od >= 0.f ? od : aodc * od;
            s0 += p0.y * od; s1 += p1.y * od; s2 += p2.y * od;
            od = g4.z * (f1.z * v0.z + f1.w * v1.z + f2.x * v2.z) + (f1.z + f1.w + f2.x) * b4.z;
            od = od >= 0.f ? od : aodc * od;
            s0 += p0.z * od; s1 += p1.z * od; s2 += p2.z * od;
            od = g4.w * (f2.y * v0.w + f2.z * v1.w + f2.w * v2.w) + (f2.y + f2.z + f2.w) * b4.w;
            od = od >= 0.f ? od : aodc * od;
            s0 += p0.w * od; s1 += p1.w * od; s2 += p2.w * od;
        }
#pragma unroll
        for (int o = 8; o > 0; o >>= 1) {
            s0 += __shfl_down_sync(0xffffffffu, s0, o, 16);
            s1 += __shfl_down_sync(0xffffffffu, s1, o, 16);
            s2 += __shfl_down_sync(0xffffffffu, s2, o, 16);
        }
        if (txx == 0) {
            const float aopc = opc_a[0];
            float off[3];
            off[0] = s0 >= 0.f ? s0 : aopc * s0;
            off[1] = s1 >= 0.f ? s1 : aopc * s1;
            off[2] = s2 >= 0.f ? s2 : aopc * s2;
#pragma unroll
            for (int k = 0; k < 3; k++) {
                float tpos = (float)t + 2.0f * (float)k + off[k];
                tpos = fminf(fmaxf(tpos, (float)t), (float)(t + 4));
                int U = (int)floorf(tpos);
                U = min(U, LP - 2);
                float Uf = (float)U;
                w0[tyy][k] = fmaxf(1.0f - fabsf(Uf - tpos), 0.0f);
                w1[tyy][k] = fmaxf(1.0f - fabsf(Uf + 1.0f - tpos), 0.0f);
                i0[tyy][k] = U - t0;
                i1[tyy][k] = U + 1 - t0;
            }
        }
    }
    __syncthreads();

    const float a2 = a2p[0];
    float lsum = 0.f, lsq = 0.f;
    for (int e = tid; e < TC * (HH / 4); e += 512) {
        int tyy = e >> 7, c = (e & 127) * 4;
        float4 f0 = *(const float4*)(dww + c * 3);
        float4 f1 = *(const float4*)(dww + c * 3 + 4);
        float4 f2 = *(const float4*)(dww + c * 3 + 8);
        float4 sa[3];
#pragma unroll
        for (int k = 0; k < 3; k++) {
            const float* ra = rows + i0[tyy][k] * HH + c;
            const float* rb = rows + i1[tyy][k] * HH + c;
            float4 va = *(const float4*)ra;
            float4 vb = *(const float4*)rb;
            float wa = w0[tyy][k], wb = w1[tyy][k];
            sa[k].x = wa * va.x + wb * vb.x;
            sa[k].y = wa * va.y + wb * vb.y;
            sa[k].z = wa * va.z + wb * vb.z;
            sa[k].w = wa * va.w + wb * vb.w;
        }
        float4 b4 = *(const float4*)(dwb + c);
        float4 g4 = *(const float4*)(sgc + c);
        float4 bc4 = *(const float4*)(sbc + c);
        float4 y;
        y.x = b4.x + g4.x * (f0.x * sa[0].x + f0.y * sa[1].x + f0.z * sa[2].x)
                   + bc4.x * (f0.x + f0.y + f0.z);
        y.y = b4.y + g4.y * (f0.w * sa[0].y + f1.x * sa[1].y + f1.y * sa[2].y)
                   + bc4.y * (f0.w + f1.x + f1.y);
        y.z = b4.z + g4.z * (f1.z * sa[0].z + f1.w * sa[1].z + f2.x * sa[2].z)
                   + bc4.z * (f1.z + f1.w + f2.x);
        y.w = b4.w + g4.w * (f2.y * sa[0].w + f2.z * sa[1].w + f2.w * sa[2].w)
                   + bc4.w * (f2.y + f2.z + f2.w);
        y.x = y.x >= 0.f ? y.x : a2 * y.x;
        y.y = y.y >= 0.f ? y.y : a2 * y.y;
        y.z = y.z >= 0.f ? y.z : a2 * y.z;
        y.w = y.w >= 0.f ? y.w : a2 * y.w;
        *(float4*)(g_p + (size_t)(m * TT + t0 + tyy) * HH + c) = y;
        lsum += y.x + y.y + y.z + y.w;
        lsq  += y.x * y.x + y.y * y.y + y.z * y.z + y.w * y.w;
    }
#pragma unroll
    for (int o = 16; o > 0; o >>= 1) {
        lsum += __shfl_down_sync(0xffffffffu, lsum, o);
        lsq  += __shfl_down_sync(0xffffffffu, lsq, o);
    }
    if ((tid & 31) == 0) {
        atomicAdd(&g_sum2[m], lsum);
        atomicAdd(&g_sq2[m],  lsq);
    }
}

// ---------------------------------------------------------------------------
// GEMM2 (tf32): out[row,b] = x[row,b] + iv2[m]*( (Wg@p)[row,b] - mu2[m]*S[b] ) + C0[b]
// 128x128 tile, 512 threads, BK=64 double-buffered, B x4-pair ldsm, gLN inline.
__global__ void __launch_bounds__(512, 1)
gemm2_kernel(const float* __restrict__ X,    // residual x [32000,128]
             float* __restrict__ out) {
    extern __shared__ float sm[];
    float* Abuf = sm;
    float* Bbuf = sm + 2 * STG64;
    const int tid = threadIdx.x;
    const int lane = tid & 31, warp = tid >> 5;
    const int warpM = warp & 3, warpN = warp >> 2;
    const int gid = lane >> 2, tig = lane & 3;
    const int rowTile = blockIdx.x * 128;

    const int aRow = (lane & 7) + ((lane >> 3) & 1) * 8;
    const int aKq  = (lane >> 4) * 4;
    const int bRow = lane & 7;
    const int bSel = (lane >> 4) & 1;
    const int bKq  = ((lane >> 3) & 1) * 4;
    const unsigned sA = (unsigned)__cvta_generic_to_shared(Abuf);
    const unsigned sB = (unsigned)__cvta_generic_to_shared(Bbuf);

    float c[2][4][4];
#pragma unroll
    for (int mt = 0; mt < 2; mt++)
#pragma unroll
        for (int nt = 0; nt < 4; nt++)
#pragma unroll
            for (int i = 0; i < 4; i++) c[mt][nt][i] = 0.f;

    const int ldRow = tid >> 4;
    const int ldQ   = (tid & 15) * 4;
#pragma unroll
    for (int i = 0; i < 4; i++) {
        int r = ldRow + i * 32;
        *(float4*)&Abuf[r * GP64 + ldQ] = *(const float4*)&g_p[(size_t)(rowTile + r) * HH + ldQ];
        *(float4*)&Bbuf[r * GP64 + ldQ] = *(const float4*)&g_wg[(size_t)r * HH + ldQ];
    }
    __syncthreads();

    int st = 0;
    for (int k0 = 0; k0 < HH; k0 += 64) {     // 8 k-tiles of 64
        const bool hn = (k0 + 64) < HH;
        float4 fa[4], fb[4];
        if (hn) {
#pragma unroll
            for (int i = 0; i < 4; i++) {
                int r = ldRow + i * 32;
                fa[i] = *(const float4*)&g_p[(size_t)(rowTile + r) * HH + k0 + 64 + ldQ];
                fb[i] = *(const float4*)&g_wg[(size_t)r * HH + k0 + 64 + ldQ];
            }
        }
        const unsigned sAs = sA + st * STG64 * 4;
        const unsigned sBs = sB + st * STG64 * 4;
#pragma unroll
        for (int ks = 0; ks < 8; ks++) {
            unsigned b[4][2];
#pragma unroll
            for (int np = 0; np < 2; np++) {
                unsigned bp[4];
                ldsm_x4(bp, sBs + ((warpN * 32 + (np * 2 + bSel) * 8 + bRow) * GP64 + ks * 8 + bKq) * 4);
                b[np * 2][0] = bp[0]; b[np * 2][1] = bp[1];
                b[np * 2 + 1][0] = bp[2]; b[np * 2 + 1][1] = bp[3];
            }
#pragma unroll
            for (int mt = 0; mt < 2; mt++) {
                unsigned a[4];
                ldsm_x4(a, sAs + ((warpM * 32 + mt * 16 + aRow) * GP64 + ks * 8 + aKq) * 4);
#pragma unroll
                for (int nt = 0; nt < 4; nt++) mma_tf32(c[mt][nt], a, b[nt]);
            }
        }
        if (hn) {
            float* An = Abuf + (st ^ 1) * STG64;
            float* Bn = Bbuf + (st ^ 1) * STG64;
#pragma unroll
            for (int i = 0; i < 4; i++) {
                int r = ldRow + i * 32;
                *(float4*)&An[r * GP64 + ldQ] = fa[i];
                *(float4*)&Bn[r * GP64 + ldQ] = fb[i];
            }
            __syncthreads();
            st ^= 1;
        }
    }

    const int m0 = rowTile / TT;
    const int rowB = (m0 + 1) * TT;
    const float nrm = (float)TT * (float)HH;
#pragma unroll
    for (int mt = 0; mt < 2; mt++) {
        int r0 = rowTile + warpM * 32 + mt * 16 + gid;
        int mmA = (r0 >= rowB) ? m0 + 1 : m0;
        int mmB = (r0 + 8 >= rowB) ? m0 + 1 : m0;
        float muA = g_sum2[mmA] / nrm;
        float ivA = 1.0f / sqrtf(g_sq2[mmA] / nrm - muA * muA + 1e-8f);
        float muB = g_sum2[mmB] / nrm;
        float ivB = 1.0f / sqrtf(g_sq2[mmB] / nrm - muB * muB + 1e-8f);
#pragma unroll
        for (int nt = 0; nt < 4; nt++) {
            int col = warpN * 32 + nt * 8 + 2 * tig;
            float S0 = g_S[col], S1 = g_S[col + 1];
            float C00 = g_C0[col], C01 = g_C0[col + 1];
            float2 x0 = *(const float2*)&X[(size_t)r0 * BBCH + col];
            float2 x8 = *(const float2*)&X[(size_t)(r0 + 8) * BBCH + col];
            *(float2*)&out[(size_t)r0 * BBCH + col] = make_float2(
                ivA * (c[mt][nt][0] - muA * S0) + C00 + x0.x,
                ivA * (c[mt][nt][1] - muA * S1) + C01 + x0.y);
            *(float2*)&out[(size_t)(r0 + 8) * BBCH + col] = make_float2(
                ivB * (c[mt][nt][2] - muB * S0) + C00 + x8.x,
                ivB * (c[mt][nt][3] - muB * S1) + C01 + x8.y);
        }
    }
}

// ---------------------------------------------------------------------------
extern "C" void kernel_launch(void* const* d_in, const int* in_sizes, int n_in,
                              void* d_out, int out_size) {
    (void)in_sizes; (void)n_in; (void)out_size;
    const float* x        = (const float*)d_in[0];
    const float* conv1_w  = (const float*)d_in[1];
    const float* prelu1_a = (const float*)d_in[2];
    const float* norm1_g  = (const float*)d_in[3];
    const float* norm1_b  = (const float*)d_in[4];
    const float* off_dw_w = (const float*)d_in[5];
    const float* odc_a    = (const float*)d_in[6];
    const float* off_pw_w = (const float*)d_in[7];
    const float* opc_a    = (const float*)d_in[8];
    const float* dw_w     = (const float*)d_in[9];
    const float* dw_b     = (const float*)d_in[10];
    const float* prelu2_a = (const float*)d_in[11];
    const float* norm2_g  = (const float*)d_in[12];
    const float* norm2_b  = (const float*)d_in[13];
    const float* pw_w     = (const float*)d_in[14];
    float* out = (float*)d_out;

    cudaFuncSetAttribute(gemm1_kernel, cudaFuncAttributeMaxDynamicSharedMemorySize, GSMEM_BYTES);
    cudaFuncSetAttribute(gemm2_kernel, cudaFuncAttributeMaxDynamicSharedMemorySize, GSMEM_BYTES);
    cudaFuncSetAttribute(offdef_kernel, cudaFuncAttributeMaxDynamicSharedMemorySize, OD_SMEM);

    wg_kernel<<<BBCH, 128>>>(pw_w, norm2_g, norm2_b);
    gemm1_kernel<<<dim3(MT / 128, HH / 128), 512, GSMEM_BYTES>>>(x, conv1_w, prelu1_a);
    offdef_kernel<<<dim3(TT / TC, MB), 512, OD_SMEM>>>(off_dw_w, odc_a, off_pw_w, opc_a,
                                                       dw_w, dw_b, prelu2_a, norm1_g, norm1_b);
    gemm2_kernel<<<MT / 128, 512, GSMEM_BYTES>>>(x, out);
}

// round 15
// speedup vs baseline: 1.2546x; 1.1208x over previous
#include <cuda_runtime.h>
#include <cuda_fp16.h>

// Problem dims
#define MB 8
#define TT 4000
#define BBCH 128
#define HH 512
#define MT (MB*TT)      // 32000 rows
#define LP (TT+4)       // padded length for deform conv (pad_tot = 4)
#define TC 32           // t-tile for fused offset+deform kernel
#define RNUM (TC+5)     // 37 smem rows
#define OD_SMEM ((2 * HH + RNUM * HH) * 4)   // 79872 B

// GEMM1 (tf32) smem geometry: BK=64, pad 68 words
#define GP64 68
#define STG64 (128 * GP64)
#define GSMEM1 (2 * 2 * STG64 * 4)      // 139264 B

// GEMM2 (fp16) smem geometry: BK=64 halves, pad 72 halves (144 B rows)
#define HP64 72
#define HSTG (128 * HP64)               // halves per operand stage
#define GSMEM2 (2 * 2 * HSTG * 2)       // 73728 B

// ---- scratch (device globals; no allocations allowed) ----
__device__ float  g_h[MT * HH];       // prelu(x@W1^T), pre-norm
__device__ __half g_ph[MT * HH];      // quantized p (fp16)
__device__ __half g_wgh[BBCH * HH];   // fp16 folded weights (pw_w * norm2_g)
__device__ float  g_S[BBCH], g_C0[BBCH];
__device__ float  g_sum1[MB], g_sq1[MB], g_sum2[MB], g_sq2[MB];

// ---- mma helpers ----
__device__ __forceinline__ void mma_tf32(float c[4], const unsigned a[4], const unsigned b[2]) {
    asm volatile(
        "mma.sync.aligned.m16n8k8.row.col.f32.tf32.tf32.f32 "
        "{%0,%1,%2,%3}, {%4,%5,%6,%7}, {%8,%9}, {%0,%1,%2,%3};"
        : "+f"(c[0]), "+f"(c[1]), "+f"(c[2]), "+f"(c[3])
        : "r"(a[0]), "r"(a[1]), "r"(a[2]), "r"(a[3]), "r"(b[0]), "r"(b[1]));
}
__device__ __forceinline__ void mma_f16(float c[4], const unsigned a[4], const unsigned b[2]) {
    asm volatile(
        "mma.sync.aligned.m16n8k16.row.col.f32.f16.f16.f32 "
        "{%0,%1,%2,%3}, {%4,%5,%6,%7}, {%8,%9}, {%0,%1,%2,%3};"
        : "+f"(c[0]), "+f"(c[1]), "+f"(c[2]), "+f"(c[3])
        : "r"(a[0]), "r"(a[1]), "r"(a[2]), "r"(a[3]), "r"(b[0]), "r"(b[1]));
}
__device__ __forceinline__ void ldsm_x4(unsigned a[4], unsigned addr) {
    asm volatile("ldmatrix.sync.aligned.m8n8.x4.shared.b16 {%0,%1,%2,%3}, [%4];"
                 : "=r"(a[0]), "=r"(a[1]), "=r"(a[2]), "=r"(a[3]) : "r"(addr));
}
__device__ __forceinline__ void cp16(unsigned dst, const void* src) {
    asm volatile("cp.async.cg.shared.global [%0], [%1], 16;" :: "r"(dst), "l"(src));
}
#define CP_COMMIT()  asm volatile("cp.async.commit_group;")
#define CP_WAIT_ALL() asm volatile("cp.async.wait_all;")

// ---------------------------------------------------------------------------
// Fold GEMM2 weights to fp16 + consistent S/C0 + zero stat accumulators.
__global__ void wg_kernel(const float* __restrict__ W,     // pw_w [128,512]
                          const float* __restrict__ gam,   // norm2_g
                          const float* __restrict__ bet) { // norm2_b
    const int b = blockIdx.x;
    const int tid = threadIdx.x;   // 128 threads
    if (b == 0 && tid < MB) {
        g_sum1[tid] = 0.f; g_sq1[tid] = 0.f;
        g_sum2[tid] = 0.f; g_sq2[tid] = 0.f;
    }
    __shared__ float rs[128], rc[128];
    float s = 0.f, c0 = 0.f;
    for (int h = tid; h < HH; h += 128) {
        float w = W[(size_t)b * HH + h];
        __half wgh = __float2half_rn(w * gam[h]);
        g_wgh[(size_t)b * HH + h] = wgh;
        s += __half2float(wgh);      // S consistent with quantized weights
        c0 += w * bet[h];
    }
    rs[tid] = s; rc[tid] = c0; __syncthreads();
    for (int o = 64; o > 0; o >>= 1) {
        if (tid < o) { rs[tid] += rs[tid + o]; rc[tid] += rc[tid + o]; }
        __syncthreads();
    }
    if (tid == 0) { g_S[b] = rs[0]; g_C0[b] = rc[0]; }
}

// ---------------------------------------------------------------------------
// GEMM1 (tf32): 128x128 tile, 512 thr, BK=64 double-buffered (unchanged R14).
__global__ void __launch_bounds__(512, 1)
gemm1_kernel(const float* __restrict__ A,   // x [32000,128]
             const float* __restrict__ W,   // conv1_w [512,128]
             const float* __restrict__ prelu_a) {
    extern __shared__ float sm[];
    float* Abuf = sm;
    float* Bbuf = sm + 2 * STG64;
    const int tid = threadIdx.x;
    const int lane = tid & 31, warp = tid >> 5;
    const int warpM = warp & 3, warpN = warp >> 2;
    const int gid = lane >> 2, tig = lane & 3;
    const int rowTile = blockIdx.x * 128, colTile = blockIdx.y * 128;

    const int aRow = (lane & 7) + ((lane >> 3) & 1) * 8;
    const int aKq  = (lane >> 4) * 4;
    const int bRow = lane & 7;
    const int bSel = (lane >> 4) & 1;
    const int bKq  = ((lane >> 3) & 1) * 4;
    const unsigned sA = (unsigned)__cvta_generic_to_shared(Abuf);
    const unsigned sB = (unsigned)__cvta_generic_to_shared(Bbuf);

    float c[2][4][4];
#pragma unroll
    for (int mt = 0; mt < 2; mt++)
#pragma unroll
        for (int nt = 0; nt < 4; nt++)
#pragma unroll
            for (int i = 0; i < 4; i++) c[mt][nt][i] = 0.f;

    const int ldRow = tid >> 4;
    const int ldQ   = (tid & 15) * 4;
#pragma unroll
    for (int i = 0; i < 4; i++) {
        int r = ldRow + i * 32;
        *(float4*)&Abuf[r * GP64 + ldQ] = *(const float4*)&A[(size_t)(rowTile + r) * BBCH + ldQ];
        *(float4*)&Bbuf[r * GP64 + ldQ] = *(const float4*)&W[(size_t)(colTile + r) * BBCH + ldQ];
    }
    __syncthreads();

    int st = 0;
    for (int kt = 0; kt < 2; kt++) {
        const bool hn = (kt == 0);
        float4 fa[4], fb[4];
        if (hn) {
#pragma unroll
            for (int i = 0; i < 4; i++) {
                int r = ldRow + i * 32;
                fa[i] = *(const float4*)&A[(size_t)(rowTile + r) * BBCH + 64 + ldQ];
                fb[i] = *(const float4*)&W[(size_t)(colTile + r) * BBCH + 64 + ldQ];
            }
        }
        const unsigned sAs = sA + st * STG64 * 4;
        const unsigned sBs = sB + st * STG64 * 4;
#pragma unroll
        for (int ks = 0; ks < 8; ks++) {
            unsigned b[4][2];
#pragma unroll
            for (int np = 0; np < 2; np++) {
                unsigned bp[4];
                ldsm_x4(bp, sBs + ((warpN * 32 + (np * 2 + bSel) * 8 + bRow) * GP64 + ks * 8 + bKq) * 4);
                b[np * 2][0] = bp[0]; b[np * 2][1] = bp[1];
                b[np * 2 + 1][0] = bp[2]; b[np * 2 + 1][1] = bp[3];
            }
#pragma unroll
            for (int mt = 0; mt < 2; mt++) {
                unsigned a[4];
                ldsm_x4(a, sAs + ((warpM * 32 + mt * 16 + aRow) * GP64 + ks * 8 + aKq) * 4);
#pragma unroll
                for (int nt = 0; nt < 4; nt++) mma_tf32(c[mt][nt], a, b[nt]);
            }
        }
        if (hn) {
            float* An = Abuf + (st ^ 1) * STG64;
            float* Bn = Bbuf + (st ^ 1) * STG64;
#pragma unroll
            for (int i = 0; i < 4; i++) {
                int r = ldRow + i * 32;
                *(float4*)&An[r * GP64 + ldQ] = fa[i];
                *(float4*)&Bn[r * GP64 + ldQ] = fb[i];
            }
            __syncthreads();
            st ^= 1;
        }
    }

    const float a = prelu_a[0];
    const int m0 = rowTile / TT;
    const int m1 = (rowTile + 127) / TT;
    const int rowB = (m0 + 1) * TT;
    float s[2] = {0.f, 0.f}, q[2] = {0.f, 0.f};
#pragma unroll
    for (int mt = 0; mt < 2; mt++) {
        int r0 = rowTile + warpM * 32 + mt * 16 + gid;
        int bin0 = (r0 >= rowB) ? 1 : 0;
        int bin8 = (r0 + 8 >= rowB) ? 1 : 0;
#pragma unroll
        for (int nt = 0; nt < 4; nt++) {
            int col = colTile + warpN * 32 + nt * 8 + 2 * tig;
            float v0 = c[mt][nt][0]; v0 = v0 >= 0.f ? v0 : a * v0;
            float v1 = c[mt][nt][1]; v1 = v1 >= 0.f ? v1 : a * v1;
            float v2 = c[mt][nt][2]; v2 = v2 >= 0.f ? v2 : a * v2;
            float v3 = c[mt][nt][3]; v3 = v3 >= 0.f ? v3 : a * v3;
            *(float2*)&g_h[(size_t)r0 * HH + col]       = make_float2(v0, v1);
            *(float2*)&g_h[(size_t)(r0 + 8) * HH + col] = make_float2(v2, v3);
            s[bin0] += v0 + v1;        q[bin0] += v0 * v0 + v1 * v1;
            s[bin8] += v2 + v3;        q[bin8] += v2 * v2 + v3 * v3;
        }
    }
#pragma unroll
    for (int o = 16; o > 0; o >>= 1) {
        s[0] += __shfl_down_sync(0xffffffffu, s[0], o);
        q[0] += __shfl_down_sync(0xffffffffu, q[0], o);
        s[1] += __shfl_down_sync(0xffffffffu, s[1], o);
        q[1] += __shfl_down_sync(0xffffffffu, q[1], o);
    }
    if ((tid & 31) == 0) {
        atomicAdd(&g_sum1[m0], s[0]);
        atomicAdd(&g_sq1[m0],  q[0]);
        if (m1 > m0) {
            atomicAdd(&g_sum1[m0 + 1], s[1]);
            atomicAdd(&g_sq1[m0 + 1],  q[1]);
        }
    }
}

// ---------------------------------------------------------------------------
// Fused offsets + deform conv: raw cp.async staging; fp16 p output; stats
// computed on the QUANTIZED p for consistency with the fp16 GEMM2.
__global__ void __launch_bounds__(512, 2)
offdef_kernel(const float* __restrict__ odww,
              const float* __restrict__ odc_a,
              const float* __restrict__ opww,
              const float* __restrict__ opc_a,
              const float* __restrict__ dww,
              const float* __restrict__ dwb,
              const float* __restrict__ a2p,
              const float* __restrict__ gam,
              const float* __restrict__ bet) {
    extern __shared__ float osm[];
    float* sgc  = osm;
    float* sbc  = osm + HH;
    float* rows = osm + 2 * HH;
    __shared__ float w0[TC][3], w1[TC][3];
    __shared__ int   i0[TC][3], i1[TC][3];

    const int m  = blockIdx.y;
    const int t0 = blockIdx.x * TC;
    const int tid = threadIdx.x;
    const float nrm = (float)TT * (float)HH;
    const float mu = g_sum1[m] / nrm;
    const float iv = 1.0f / sqrtf(g_sq1[m] / nrm - mu * mu + 1e-8f);

    const float* base = g_h + (size_t)m * TT * HH;
    const unsigned sRows = (unsigned)__cvta_generic_to_shared(rows);
    for (int e = tid; e < RNUM * (HH / 4); e += 512) {
        int j = e >> 7, c4 = e & 127;
        int src = t0 - 2 + j;
        if (src < 0) src = -src;
        if (src >= TT) src = 2 * TT - 2 - src;
        cp16(sRows + (j * HH + c4 * 4) * 4, base + (size_t)src * HH + c4 * 4);
    }
    CP_COMMIT();

    for (int c = tid; c < HH; c += 512) {
        float gc = gam[c] * iv;
        sgc[c] = gc;
        sbc[c] = bet[c] - gc * mu;
    }
    CP_WAIT_ALL();
    __syncthreads();

    {
        const int tyy = tid >> 4, txx = tid & 15;
        const int t = t0 + tyy;
        const float* r0 = rows + (tyy + 1) * HH;
        const float* r1 = rows + (tyy + 2) * HH;
        const float* r2 = rows + (tyy + 3) * HH;
        const float aodc = odc_a[0];
        float s0 = 0.f, s1 = 0.f, s2 = 0.f;
#pragma unroll
        for (int it = 0; it < 8; it++) {
            int c = (txx + it * 16) * 4;
            float4 v0 = *(const float4*)(r0 + c);
            float4 v1 = *(const float4*)(r1 + c);
            float4 v2 = *(const float4*)(r2 + c);
            float4 f0 = *(const float4*)(odww + c * 3);
            float4 f1 = *(const float4*)(odww + c * 3 + 4);
            float4 f2 = *(const float4*)(odww + c * 3 + 8);
            float4 p0 = *(const float4*)(opww + c);
            float4 p1 = *(const float4*)(opww + HH + c);
            float4 p2 = *(const float4*)(opww + 2 * HH + c);
            float4 g4 = *(const float4*)(sgc + c);
            float4 b4 = *(const float4*)(sbc + c);
            float od;
            od = g4.x * (f0.x * v0.x + f0.y * v1.x + f0.z * v2.x) + (f0.x + f0.y + f0.z) * b4.x;
            od = od >= 0.f ? od : aodc * od;
            s0 += p0.x * od; s1 += p1.x * od; s2 += p2.x * od;
            od = g4.y * (f0.w * v0.y + f1.x * v1.y + f1.y * v2.y) + (f0.w + f1.x + f1.y) * b4.y;
            od = od >= 0.f ? od : aodc * od;
            s0 += p0.y * od; s1 += p1.y * od; s2 += p2.y * od;
            od = g4.z * (f1.z * v0.z + f1.w * v1.z + f2.x * v2.z) + (f1.z + f1.w + f2.x) * b4.z;
            od = od >= 0.f ? od : aodc * od;
            s0 += p0.z * od; s1 += p1.z * od; s2 += p2.z * od;
            od = g4.w * (f2.y * v0.w + f2.z * v1.w + f2.w * v2.w) + (f2.y + f2.z + f2.w) * b4.w;
            od = od >= 0.f ? od : aodc * od;
            s0 += p0.w * od; s1 += p1.w * od; s2 += p2.w * od;
        }
#pragma unroll
        for (int o = 8; o > 0; o >>= 1) {
            s0 += __shfl_down_sync(0xffffffffu, s0, o, 16);
            s1 += __shfl_down_sync(0xffffffffu, s1, o, 16);
            s2 += __shfl_down_sync(0xffffffffu, s2, o, 16);
        }
        if (txx == 0) {
            const float aopc = opc_a[0];
            float off[3];
            off[0] = s0 >= 0.f ? s0 : aopc * s0;
            off[1] = s1 >= 0.f ? s1 : aopc * s1;
            off[2] = s2 >= 0.f ? s2 : aopc * s2;
#pragma unroll
            for (int k = 0; k < 3; k++) {
                float tpos = (float)t + 2.0f * (float)k + off[k];
                tpos = fminf(fmaxf(tpos, (float)t), (float)(t + 4));
                int U = (int)floorf(tpos);
                U = min(U, LP - 2);
                float Uf = (float)U;
                w0[tyy][k] = fmaxf(1.0f - fabsf(Uf - tpos), 0.0f);
                w1[tyy][k] = fmaxf(1.0f - fabsf(Uf + 1.0f - tpos), 0.0f);
                i0[tyy][k] = U - t0;
                i1[tyy][k] = U + 1 - t0;
            }
        }
    }
    __syncthreads();

    const float a2 = a2p[0];
    float lsum = 0.f, lsq = 0.f;
    for (int e = tid; e < TC * (HH / 4); e += 512) {
        int tyy = e >> 7, c = (e & 127) * 4;
        float4 f0 = *(const float4*)(dww + c * 3);
        float4 f1 = *(const float4*)(dww + c * 3 + 4);
        float4 f2 = *(const float4*)(dww + c * 3 + 8);
        float4 sa[3];
#pragma unroll
        for (int k = 0; k < 3; k++) {
            const float* ra = rows + i0[tyy][k] * HH + c;
            const float* rb = rows + i1[tyy][k] * HH + c;
            float4 va = *(const float4*)ra;
            float4 vb = *(const float4*)rb;
            float wa = w0[tyy][k], wb = w1[tyy][k];
            sa[k].x = wa * va.x + wb * vb.x;
            sa[k].y = wa * va.y + wb * vb.y;
            sa[k].z = wa * va.z + wb * vb.z;
            sa[k].w = wa * va.w + wb * vb.w;
        }
        float4 b4 = *(const float4*)(dwb + c);
        float4 g4 = *(const float4*)(sgc + c);
        float4 bc4 = *(const float4*)(sbc + c);
        float4 y;
        y.x = b4.x + g4.x * (f0.x * sa[0].x + f0.y * sa[1].x + f0.z * sa[2].x)
                   + bc4.x * (f0.x + f0.y + f0.z);
        y.y = b4.y + g4.y * (f0.w * sa[0].y + f1.x * sa[1].y + f1.y * sa[2].y)
                   + bc4.y * (f0.w + f1.x + f1.y);
        y.z = b4.z + g4.z * (f1.z * sa[0].z + f1.w * sa[1].z + f2.x * sa[2].z)
                   + bc4.z * (f1.z + f1.w + f2.x);
        y.w = b4.w + g4.w * (f2.y * sa[0].w + f2.z * sa[1].w + f2.w * sa[2].w)
                   + bc4.w * (f2.y + f2.z + f2.w);
        y.x = y.x >= 0.f ? y.x : a2 * y.x;
        y.y = y.y >= 0.f ? y.y : a2 * y.y;
        y.z = y.z >= 0.f ? y.z : a2 * y.z;
        y.w = y.w >= 0.f ? y.w : a2 * y.w;
        // Quantize to fp16; stats on quantized values (consistent with GEMM2).
        __half2 h0 = __floats2half2_rn(y.x, y.y);
        __half2 h1 = __floats2half2_rn(y.z, y.w);
        *(__half2*)(g_ph + (size_t)(m * TT + t0 + tyy) * HH + c)     = h0;
        *(__half2*)(g_ph + (size_t)(m * TT + t0 + tyy) * HH + c + 2) = h1;
        float2 q0 = __half22float2(h0);
        float2 q1 = __half22float2(h1);
        lsum += q0.x + q0.y + q1.x + q1.y;
        lsq  += q0.x * q0.x + q0.y * q0.y + q1.x * q1.x + q1.y * q1.y;
    }
#pragma unroll
    for (int o = 16; o > 0; o >>= 1) {
        lsum += __shfl_down_sync(0xffffffffu, lsum, o);
        lsq  += __shfl_down_sync(0xffffffffu, lsq, o);
    }
    if ((tid & 31) == 0) {
        atomicAdd(&g_sum2[m], lsum);
        atomicAdd(&g_sq2[m],  lsq);
    }
}

// ---------------------------------------------------------------------------
// GEMM2 (fp16 m16n8k16, fp32 accum): 128x128 tile, 512 threads, BK=64 halves,
// double-buffered, B fragments as x4 pairs, gLN2 folded epilogue + residual.
__global__ void __launch_bounds__(512, 1)
gemm2_kernel(const float* __restrict__ X,    // residual x [32000,128]
             float* __restrict__ out) {
    extern __shared__ __half hsm[];
    __half* Abuf = hsm;                 // [2][128][HP64]
    __half* Bbuf = hsm + 2 * HSTG;
    const int tid = threadIdx.x;
    const int lane = tid & 31, warp = tid >> 5;
    const int warpM = warp & 3, warpN = warp >> 2;
    const int gid = lane >> 2, tig = lane & 3;
    const int rowTile = blockIdx.x * 128;

    // fp16 ldsm lane addressing (byte offsets within a 32-halves k-tile row = 144B rows)
    const int aRow  = (lane & 7) + ((lane >> 3) & 1) * 8;
    const int aByte = ((lane >> 4) & 1) * 16;
    const int bRow  = lane & 7;
    const int bByte = ((lane >> 3) & 1) * 16;
    const int bTile = (lane >> 4) & 1;
    const unsigned sA = (unsigned)__cvta_generic_to_shared(Abuf);
    const unsigned sB = (unsigned)__cvta_generic_to_shared(Bbuf);

    float c[2][4][4];
#pragma unroll
    for (int mt = 0; mt < 2; mt++)
#pragma unroll
        for (int nt = 0; nt < 4; nt++)
#pragma unroll
            for (int i = 0; i < 4; i++) c[mt][nt][i] = 0.f;

    // Staging: 128 rows x 64 halves = 1024 x 16B chunks per operand, 2/thread.
    const int ldRow = tid >> 3;          // 0..63 -> two row groups
    const int ldCh  = (tid & 7) * 8;     // half offset within 64
    const int ldRow2 = ldRow + 64;
    {
        *(float4*)&Abuf[ldRow  * HP64 + ldCh] = *(const float4*)&g_ph[(size_t)(rowTile + ldRow ) * HH + ldCh];
        *(float4*)&Abuf[ldRow2 * HP64 + ldCh] = *(const float4*)&g_ph[(size_t)(rowTile + ldRow2) * HH + ldCh];
        *(float4*)&Bbuf[ldRow  * HP64 + ldCh] = *(const float4*)&g_wgh[(size_t)ldRow  * HH + ldCh];
        *(float4*)&Bbuf[ldRow2 * HP64 + ldCh] = *(const float4*)&g_wgh[(size_t)ldRow2 * HH + ldCh];
    }
    __syncthreads();

    int st = 0;
    for (int k0 = 0; k0 < HH; k0 += 64) {     // 8 k-tiles of 64 halves
        const bool hn = (k0 + 64) < HH;
        float4 fa0, fa1, fb0, fb1;
        if (hn) {
            fa0 = *(const float4*)&g_ph[(size_t)(rowTile + ldRow ) * HH + k0 + 64 + ldCh];
            fa1 = *(const float4*)&g_ph[(size_t)(rowTile + ldRow2) * HH + k0 + 64 + ldCh];
            fb0 = *(const float4*)&g_wgh[(size_t)ldRow  * HH + k0 + 64 + ldCh];
            fb1 = *(const float4*)&g_wgh[(size_t)ldRow2 * HH + k0 + 64 + ldCh];
        }
        const unsigned sAs = sA + st * HSTG * 2;
        const unsigned sBs = sB + st * HSTG * 2;
#pragma unroll
        for (int ks = 0; ks < 4; ks++) {      // 4 k16-steps per tile
            unsigned b[4][2];
#pragma unroll
            for (int np = 0; np < 2; np++) {
                unsigned bp[4];
                ldsm_x4(bp, sBs + (warpN * 32 + (np * 2 + bTile) * 8 + bRow) * (HP64 * 2) + ks * 32 + bByte);
                b[np * 2][0] = bp[0]; b[np * 2][1] = bp[1];
                b[np * 2 + 1][0] = bp[2]; b[np * 2 + 1][1] = bp[3];
            }
#pragma unroll
            for (int mt = 0; mt < 2; mt++) {
                unsigned a[4];
                ldsm_x4(a, sAs + (warpM * 32 + mt * 16 + aRow) * (HP64 * 2) + ks * 32 + aByte);
#pragma unroll
                for (int nt = 0; nt < 4; nt++) mma_f16(c[mt][nt], a, b[nt]);
            }
        }
        if (hn) {
            __half* An = Abuf + (st ^ 1) * HSTG;
            __half* Bn = Bbuf + (st ^ 1) * HSTG;
            *(float4*)&An[ldRow  * HP64 + ldCh] = fa0;
            *(float4*)&An[ldRow2 * HP64 + ldCh] = fa1;
            *(float4*)&Bn[ldRow  * HP64 + ldCh] = fb0;
            *(float4*)&Bn[ldRow2 * HP64 + ldCh] = fb1;
            __syncthreads();
            st ^= 1;
        }
    }

    const int m0 = rowTile / TT;
    const int rowB = (m0 + 1) * TT;
    const float nrm = (float)TT * (float)HH;
#pragma unroll
    for (int mt = 0; mt < 2; mt++) {
        int r0 = rowTile + warpM * 32 + mt * 16 + gid;
        int mmA = (r0 >= rowB) ? m0 + 1 : m0;
        int mmB = (r0 + 8 >= rowB) ? m0 + 1 : m0;
        float muA = g_sum2[mmA] / nrm;
        float ivA = 1.0f / sqrtf(g_sq2[mmA] / nrm - muA * muA + 1e-8f);
        float muB = g_sum2[mmB] / nrm;
        float ivB = 1.0f / sqrtf(g_sq2[mmB] / nrm - muB * muB + 1e-8f);
#pragma unroll
        for (int nt = 0; nt < 4; nt++) {
            int col = warpN * 32 + nt * 8 + 2 * tig;
            float S0 = g_S[col], S1 = g_S[col + 1];
            float C00 = g_C0[col], C01 = g_C0[col + 1];
            float2 x0 = *(const float2*)&X[(size_t)r0 * BBCH + col];
            float2 x8 = *(const float2*)&X[(size_t)(r0 + 8) * BBCH + col];
            *(float2*)&out[(size_t)r0 * BBCH + col] = make_float2(
                ivA * (c[mt][nt][0] - muA * S0) + C00 + x0.x,
                ivA * (c[mt][nt][1] - muA * S1) + C01 + x0.y);
            *(float2*)&out[(size_t)(r0 + 8) * BBCH + col] = make_float2(
                ivB * (c[mt][nt][2] - muB * S0) + C00 + x8.x,
                ivB * (c[mt][nt][3] - muB * S1) + C01 + x8.y);
        }
    }
}

// ---------------------------------------------------------------------------
extern "C" void kernel_launch(void* const* d_in, const int* in_sizes, int n_in,
                              void* d_out, int out_size) {
    (void)in_sizes; (void)n_in; (void)out_size;
    const float* x        = (const float*)d_in[0];
    const float* conv1_w  = (const float*)d_in[1];
    const float* prelu1_a = (const float*)d_in[2];
    const float* norm1_g  = (const float*)d_in[3];
    const float* norm1_b  = (const float*)d_in[4];
    const float* off_dw_w = (const float*)d_in[5];
    const float* odc_a    = (const float*)d_in[6];
    const float* off_pw_w = (const float*)d_in[7];
    const float* opc_a    = (const float*)d_in[8];
    const float* dw_w     = (const float*)d_in[9];
    const float* dw_b     = (const float*)d_in[10];
    const float* prelu2_a = (const float*)d_in[11];
    const float* norm2_g  = (const float*)d_in[12];
    const float* norm2_b  = (const float*)d_in[13];
    const float* pw_w     = (const float*)d_in[14];
    float* out = (float*)d_out;

    cudaFuncSetAttribute(gemm1_kernel, cudaFuncAttributeMaxDynamicSharedMemorySize, GSMEM1);
    cudaFuncSetAttribute(gemm2_kernel, cudaFuncAttributeMaxDynamicSharedMemorySize, GSMEM2);
    cudaFuncSetAttribute(offdef_kernel, cudaFuncAttributeMaxDynamicSharedMemorySize, OD_SMEM);

    wg_kernel<<<BBCH, 128>>>(pw_w, norm2_g, norm2_b);
    gemm1_kernel<<<dim3(MT / 128, HH / 128), 512, GSMEM1>>>(x, conv1_w, prelu1_a);
    offdef_kernel<<<dim3(TT / TC, MB), 512, OD_SMEM>>>(off_dw_w, odc_a, off_pw_w, opc_a,
                                                       dw_w, dw_b, prelu2_a, norm1_g, norm1_b);
    gemm2_kernel<<<MT / 128, 512, GSMEM2>>>(x, out);
}